// round 13
// baseline (speedup 1.0000x reference)
#include <cuda_runtime.h>
#include <cuda_bf16.h>
#include <cstdint>
#include <cstddef>

// Problem dims (fixed by the reference)
#define Bb 2
#define NN 4096
#define FF 256
#define HH 1024
#define NWORDS 128   // NN/32

// ---------------- scratch (device globals; no allocation allowed) ----------
__device__ __align__(16) uint32_t g_bits[Bb][NN][NWORDS];   // 4 MB adjacency bitmask
__device__ __align__(16) float g_Wh [Bb * NN * FF];         // current layer Wh
__device__ __align__(16) float g_h1 [Bb * NN * FF];         // GAT1 out
__device__ __align__(16) float g_h2 [Bb * NN * FF];         // GAT2 out
__device__ __align__(16) float g_hln[Bb * NN * FF];         // after LN1
__device__ __align__(16) float g_mid[Bb * NN * HH];         // FF hidden
__device__ __align__(16) float g_ff [Bb * NN * FF];         // FF out
__device__ __align__(16) float g_sc1[Bb * NN];
__device__ __align__(16) float g_sc2[Bb * NN];
__device__ __align__(16) float2 g_c2[Bb * NN];              // {sc2[j], c[j]}

// ---------------- helpers ---------------------------------------------------
__device__ __forceinline__ uint32_t f2tf(float x) {
    uint32_t u;
    asm("cvt.rna.tf32.f32 %0, %1;" : "=r"(u) : "f"(x));
    return u;
}

__device__ __forceinline__ void mma_tf32(float c[4],
        const uint32_t a[4], const uint32_t b[2]) {
    asm volatile(
        "mma.sync.aligned.m16n8k8.row.col.f32.tf32.tf32.f32 "
        "{%0,%1,%2,%3}, {%4,%5,%6,%7}, {%8,%9}, {%0,%1,%2,%3};\n"
        : "+f"(c[0]), "+f"(c[1]), "+f"(c[2]), "+f"(c[3])
        : "r"(a[0]), "r"(a[1]), "r"(a[2]), "r"(a[3]), "r"(b[0]), "r"(b[1]));
}

#define SAS 36    // sA row stride (floats): conflict-free A-frag loads
#define SBS 136   // sB row stride (floats): (r*136+g)%32 = r*8+g -> conflict-free

// ---------------- 1) pack adjacency into bitmask ----------------------------
__global__ void pack_bits(const int* __restrict__ adj) {
    // one block per (b,i) row; blockIdx.x = b*NN + i
    const int warp = threadIdx.x >> 5, lane = threadIdx.x & 31;
    const size_t base = (size_t)blockIdx.x * NN;
    uint32_t* gb = &g_bits[0][0][0];
    for (int t = warp; t < NWORDS; t += 8) {
        int j = t * 32 + lane;
        unsigned m = __ballot_sync(0xffffffffu, adj[base + j] > 0);
        if (lane == 0) gb[(size_t)blockIdx.x * NWORDS + t] = m;
    }
}

// ---------------- 2) per-row attention scalars sc1,sc2 ----------------------
__global__ __launch_bounds__(256)
void sc_kernel(const float* __restrict__ Wh, const float* __restrict__ a,
               float* __restrict__ sc1, float* __restrict__ sc2) {
    int row = blockIdx.x * 8 + (threadIdx.x >> 5);
    int lane = threadIdx.x & 31;
    const float* wp = Wh + (size_t)row * FF;
    float d1 = 0.f, d2 = 0.f;
#pragma unroll
    for (int q = 0; q < 8; q++) {
        int f = lane + q * 32;
        float wv = wp[f];
        d1 += wv * __ldg(&a[f]);
        d2 += wv * __ldg(&a[FF + f]);
    }
#pragma unroll
    for (int o = 16; o; o >>= 1) {
        d1 += __shfl_xor_sync(0xffffffffu, d1, o);
        d2 += __shfl_xor_sync(0xffffffffu, d2, o);
    }
    if (lane == 0) { sc1[row] = d1; sc2[row] = d2; }
}

// ---------------- 3) column softmax stats: c[j] = m[j] + log(colsum[j]) -----
// grid (NWORDS, Bb), 256 threads; warp w scans i in [w*512,(w+1)*512), lane=j bit
__global__ __launch_bounds__(256)
void colstats(const float* __restrict__ sc1, const float* __restrict__ sc2,
              float2* __restrict__ c2) {
    const int b = blockIdx.y, wi = blockIdx.x;
    const int w = threadIdx.x >> 5, lane = threadIdx.x & 31;
    __shared__ float s1[NN];
    __shared__ float red[8][32];
    for (int i = threadIdx.x; i < NN; i += 256) s1[i] = sc1[b * NN + i];
    __syncthreads();

    const uint32_t* bw = &g_bits[b][0][wi];   // stride NWORDS per row
    const uint32_t sel = 1u << lane;
    const int i0 = w * 512;

    float mx = -3.0e38f;
#pragma unroll 4
    for (int i = i0; i < i0 + 512; i++) {
        uint32_t wv = __ldg(&bw[(size_t)i * NWORDS]);
        if (wv & sel) mx = fmaxf(mx, s1[i]);
    }
    red[w][lane] = mx;
    __syncthreads();
    float gmx = red[0][lane];
#pragma unroll
    for (int k = 1; k < 8; k++) gmx = fmaxf(gmx, red[k][lane]);

    const int j = wi * 32 + lane;
    const float s2 = __ldg(&sc2[b * NN + j]);
    float u = gmx + s2;
    float mcol = u > 0.f ? u : 0.2f * u;           // lrelu(max) = max lrelu

    float sum = 0.f;
#pragma unroll 4
    for (int i = i0; i < i0 + 512; i++) {
        uint32_t wv = __ldg(&bw[(size_t)i * NWORDS]);
        if (wv & sel) {
            float t = s1[i] + s2;
            float s = t > 0.f ? t : 0.2f * t;
            sum += __expf(s - mcol);
        }
    }
    __syncthreads();
    red[w][lane] = sum;
    __syncthreads();
    if (w == 0) {
        float tot = 0.f;
#pragma unroll
        for (int k = 0; k < 8; k++) tot += red[k][lane];
        float c = (tot > 0.f) ? (mcol + __logf(tot)) : 0.f;
        c2[b * NN + j] = make_float2(s2, c);
    }
}

// ---------------- 4) generic TF32 GEMM: C = A[M,K] @ B[K,N] (+epilogue) -----
// EPI: 0 = none, 1 = bias+relu, 2 = bias.  SPLIT: hi/lo 3-mma fp32 emulation.
template<int EPI, bool SPLIT>
__global__ __launch_bounds__(256, 1)
void gemm_tf32(const float* __restrict__ A, const float* __restrict__ B,
               const float* __restrict__ bias, float* __restrict__ C,
               int M, int Ncols, int K) {
    __shared__ __align__(16) float sA[128 * SAS];
    __shared__ __align__(16) float sB[32 * SBS];
    const int tid = threadIdx.x;
    const int i0 = blockIdx.x * 128;
    const int n0 = blockIdx.y * 128;
    const int w = tid >> 5, lane = tid & 31;
    const int wm = w >> 2, wn = w & 3;
    const int g = lane >> 2, r = lane & 3;

    float acc[4][4][4];
#pragma unroll
    for (int a = 0; a < 4; a++)
#pragma unroll
        for (int bq = 0; bq < 4; bq++)
#pragma unroll
            for (int cq = 0; cq < 4; cq++) acc[a][bq][cq] = 0.f;

    for (int kt = 0; kt < K; kt += 32) {
#pragma unroll
        for (int t = 0; t < 4; t++) {
            int idx = tid + t * 256;
            int row = idx >> 3, c4 = (idx & 7) << 2;
            float4 v = *reinterpret_cast<const float4*>(
                &A[(size_t)(i0 + row) * K + kt + c4]);
            *reinterpret_cast<float4*>(&sA[row * SAS + c4]) = v;
        }
#pragma unroll
        for (int t = 0; t < 4; t++) {
            int idx = tid + t * 256;
            int row = idx >> 5, c4 = (idx & 31) << 2;
            float4 v = *reinterpret_cast<const float4*>(
                &B[(size_t)(kt + row) * Ncols + n0 + c4]);
            *reinterpret_cast<float4*>(&sB[row * SBS + c4]) = v;
        }
        __syncthreads();
#pragma unroll
        for (int kk = 0; kk < 4; kk++) {
            uint32_t ah[4][4], al[4][4], bh[4][2], bl[4][2];
#pragma unroll
            for (int mt = 0; mt < 4; mt++) {
                int base = wm * 64 + mt * 16;
                float v0 = sA[(base + g)     * SAS + kk * 8 + r];
                float v1 = sA[(base + g + 8) * SAS + kk * 8 + r];
                float v2 = sA[(base + g)     * SAS + kk * 8 + r + 4];
                float v3 = sA[(base + g + 8) * SAS + kk * 8 + r + 4];
                ah[mt][0] = f2tf(v0); ah[mt][1] = f2tf(v1);
                ah[mt][2] = f2tf(v2); ah[mt][3] = f2tf(v3);
                if (SPLIT) {
                    al[mt][0] = f2tf(v0 - __uint_as_float(ah[mt][0]));
                    al[mt][1] = f2tf(v1 - __uint_as_float(ah[mt][1]));
                    al[mt][2] = f2tf(v2 - __uint_as_float(ah[mt][2]));
                    al[mt][3] = f2tf(v3 - __uint_as_float(ah[mt][3]));
                }
            }
#pragma unroll
            for (int nt = 0; nt < 4; nt++) {
                int nb = wn * 32 + nt * 8 + g;
                float v0 = sB[(kk * 8 + r)     * SBS + nb];
                float v1 = sB[(kk * 8 + r + 4) * SBS + nb];
                bh[nt][0] = f2tf(v0); bh[nt][1] = f2tf(v1);
                if (SPLIT) {
                    bl[nt][0] = f2tf(v0 - __uint_as_float(bh[nt][0]));
                    bl[nt][1] = f2tf(v1 - __uint_as_float(bh[nt][1]));
                }
            }
#pragma unroll
            for (int mt = 0; mt < 4; mt++)
#pragma unroll
                for (int nt = 0; nt < 4; nt++) {
                    mma_tf32(acc[mt][nt], ah[mt], bh[nt]);
                    if (SPLIT) {
                        mma_tf32(acc[mt][nt], ah[mt], bl[nt]);
                        mma_tf32(acc[mt][nt], al[mt], bh[nt]);
                    }
                }
        }
        __syncthreads();
    }
#pragma unroll
    for (int mt = 0; mt < 4; mt++) {
#pragma unroll
        for (int nt = 0; nt < 4; nt++) {
            int row = i0 + wm * 64 + mt * 16 + g;
            int col = n0 + wn * 32 + nt * 8 + 2 * r;
            float b0 = 0.f, b1 = 0.f;
            if (EPI != 0) { b0 = __ldg(&bias[col]); b1 = __ldg(&bias[col + 1]); }
            float x0 = acc[mt][nt][0] + b0, x1 = acc[mt][nt][1] + b1;
            float x2 = acc[mt][nt][2] + b0, x3 = acc[mt][nt][3] + b1;
            if (EPI == 1) {
                x0 = fmaxf(x0, 0.f); x1 = fmaxf(x1, 0.f);
                x2 = fmaxf(x2, 0.f); x3 = fmaxf(x3, 0.f);
            }
            *reinterpret_cast<float2*>(&C[(size_t)row * Ncols + col]) =
                make_float2(x0, x1);
            *reinterpret_cast<float2*>(&C[(size_t)(row + 8) * Ncols + col]) =
                make_float2(x2, x3);
        }
    }
}

// ---------------- 5) aggregation: out = E @ Wh, E generated on the fly ------
// E[i,j] = adj(i,j) ? exp(lrelu(sc1[i]+sc2[j]) - c[j]) : 0
__global__ __launch_bounds__(256, 1)
void agg_tf32(const float* __restrict__ Wh, const float* __restrict__ sc1,
              const float2* __restrict__ c2, float* __restrict__ out) {
    __shared__ __align__(16) float sA[128 * SAS];
    __shared__ __align__(16) float sB[32 * SBS];
    __shared__ float s1[128];
    const int tid = threadIdx.x;
    const int b = blockIdx.z;
    const int i0 = blockIdx.x * 128;
    const int n0 = blockIdx.y * 128;
    const int w = tid >> 5, lane = tid & 31;
    const int wm = w >> 2, wn = w & 3;
    const int g = lane >> 2, r = lane & 3;

    if (tid < 128) s1[tid] = sc1[b * NN + i0 + tid];
    const float* WhB = Wh + (size_t)b * NN * FF;

    float acc[4][4][4];
#pragma unroll
    for (int a = 0; a < 4; a++)
#pragma unroll
        for (int bq = 0; bq < 4; bq++)
#pragma unroll
            for (int cq = 0; cq < 4; cq++) acc[a][bq][cq] = 0.f;
    __syncthreads();

    const int arow = tid >> 1;
    const int jl0  = (tid & 1) << 4;
    const float v1 = s1[arow];

    for (int kt = 0; kt < NN / 32; kt++) {
        const int j0 = kt * 32;
        // --- generate E tile [128 x 32] into sA (fp32) ---
        {
            uint32_t word = g_bits[b][i0 + arow][kt] >> jl0;
            float ev[16];
#pragma unroll
            for (int q = 0; q < 16; q++) {
                float e = 0.f;
                if ((word >> q) & 1u) {
                    float2 p = __ldg(&c2[b * NN + j0 + jl0 + q]);
                    float u = v1 + p.x;
                    float s = u > 0.f ? u : 0.2f * u;
                    e = __expf(s - p.y);
                }
                ev[q] = e;
            }
            float4* dst = reinterpret_cast<float4*>(&sA[arow * SAS + jl0]);
            dst[0] = make_float4(ev[0],  ev[1],  ev[2],  ev[3]);
            dst[1] = make_float4(ev[4],  ev[5],  ev[6],  ev[7]);
            dst[2] = make_float4(ev[8],  ev[9],  ev[10], ev[11]);
            dst[3] = make_float4(ev[12], ev[13], ev[14], ev[15]);
        }
        // --- load Wh tile [32 x 128] (L2-resident) ---
#pragma unroll
        for (int t = 0; t < 4; t++) {
            int idx = tid + t * 256;
            int row = idx >> 5, c4 = (idx & 31) << 2;
            float4 v = *reinterpret_cast<const float4*>(
                &WhB[(size_t)(j0 + row) * FF + n0 + c4]);
            *reinterpret_cast<float4*>(&sB[row * SBS + c4]) = v;
        }
        __syncthreads();
#pragma unroll
        for (int kk = 0; kk < 4; kk++) {
            uint32_t af[4][4], bf[4][2];
#pragma unroll
            for (int mt = 0; mt < 4; mt++) {
                int base = wm * 64 + mt * 16;
                af[mt][0] = f2tf(sA[(base + g)     * SAS + kk * 8 + r]);
                af[mt][1] = f2tf(sA[(base + g + 8) * SAS + kk * 8 + r]);
                af[mt][2] = f2tf(sA[(base + g)     * SAS + kk * 8 + r + 4]);
                af[mt][3] = f2tf(sA[(base + g + 8) * SAS + kk * 8 + r + 4]);
            }
#pragma unroll
            for (int nt = 0; nt < 4; nt++) {
                int nb = wn * 32 + nt * 8 + g;
                bf[nt][0] = f2tf(sB[(kk * 8 + r)     * SBS + nb]);
                bf[nt][1] = f2tf(sB[(kk * 8 + r + 4) * SBS + nb]);
            }
#pragma unroll
            for (int mt = 0; mt < 4; mt++)
#pragma unroll
                for (int nt = 0; nt < 4; nt++)
                    mma_tf32(acc[mt][nt], af[mt], bf[nt]);
        }
        __syncthreads();
    }
#pragma unroll
    for (int mt = 0; mt < 4; mt++) {
#pragma unroll
        for (int nt = 0; nt < 4; nt++) {
            int row = i0 + wm * 64 + mt * 16 + g;
            int col = n0 + wn * 32 + nt * 8 + 2 * r;
            size_t o0 = ((size_t)b * NN + row) * FF + col;
            *reinterpret_cast<float2*>(&out[o0]) =
                make_float2(acc[mt][nt][0], acc[mt][nt][1]);
            *reinterpret_cast<float2*>(&out[o0 + (size_t)8 * FF]) =
                make_float2(acc[mt][nt][2], acc[mt][nt][3]);
        }
    }
}

// ---------------- 6) residual + layernorm -----------------------------------
__global__ __launch_bounds__(256)
void add_ln(const float* __restrict__ resid, const float* __restrict__ h,
            const float* __restrict__ gam, const float* __restrict__ bet,
            float* __restrict__ out) {
    int row = blockIdx.x * 8 + (threadIdx.x >> 5);
    int lane = threadIdx.x & 31;
    const float* rp = resid + (size_t)row * FF;
    const float* hp = h + (size_t)row * FF;
    float v[8];
    float sum = 0.f, sq = 0.f;
#pragma unroll
    for (int q = 0; q < 8; q++) {
        float xv = rp[lane + q * 32] + hp[lane + q * 32];
        v[q] = xv; sum += xv; sq += xv * xv;
    }
#pragma unroll
    for (int o = 16; o; o >>= 1) {
        sum += __shfl_xor_sync(0xffffffffu, sum, o);
        sq  += __shfl_xor_sync(0xffffffffu, sq, o);
    }
    float mean = sum * (1.f / FF);
    float var = sq * (1.f / FF) - mean * mean;
    float rstd = rsqrtf(var + 1e-5f);
#pragma unroll
    for (int q = 0; q < 8; q++) {
        int f = lane + q * 32;
        out[(size_t)row * FF + f] = (v[q] - mean) * rstd * __ldg(&gam[f]) + __ldg(&bet[f]);
    }
}

// ---------------- host orchestration ----------------------------------------
extern "C" void kernel_launch(void* const* d_in, const int* in_sizes, int n_in,
                              void* d_out, int out_size) {
    const float* x    = (const float*)d_in[0];
    const int*   adj  = (const int*)  d_in[1];
    const float* W1   = (const float*)d_in[2];
    const float* a1   = (const float*)d_in[3];
    const float* W2   = (const float*)d_in[4];
    const float* a2   = (const float*)d_in[5];
    const float* wff1 = (const float*)d_in[6];
    const float* bff1 = (const float*)d_in[7];
    const float* wff2 = (const float*)d_in[8];
    const float* bff2 = (const float*)d_in[9];
    const float* gln1 = (const float*)d_in[10];
    const float* bln1 = (const float*)d_in[11];
    const float* gln2 = (const float*)d_in[12];
    const float* bln2 = (const float*)d_in[13];
    float* out = (float*)d_out;

    float *pWh, *pH1, *pH2, *pHln, *pMid, *pFFo, *pSc1, *pSc2;
    float2* pC2;
    cudaGetSymbolAddress((void**)&pWh,  g_Wh);
    cudaGetSymbolAddress((void**)&pH1,  g_h1);
    cudaGetSymbolAddress((void**)&pH2,  g_h2);
    cudaGetSymbolAddress((void**)&pHln, g_hln);
    cudaGetSymbolAddress((void**)&pMid, g_mid);
    cudaGetSymbolAddress((void**)&pFFo, g_ff);
    cudaGetSymbolAddress((void**)&pSc1, g_sc1);
    cudaGetSymbolAddress((void**)&pSc2, g_sc2);
    cudaGetSymbolAddress((void**)&pC2,  g_c2);

    const int M = Bb * NN;   // 8192

    pack_bits<<<Bb * NN, 256>>>(adj);

    // ---- GAT layer 1 ----
    gemm_tf32<0, true><<<dim3(M / 128, FF / 128), 256>>>(x, W1, nullptr, pWh, M, FF, FF);
    sc_kernel<<<M / 8, 256>>>(pWh, a1, pSc1, pSc2);
    colstats<<<dim3(NWORDS, Bb), 256>>>(pSc1, pSc2, pC2);
    agg_tf32<<<dim3(NN / 128, FF / 128, Bb), 256>>>(pWh, pSc1, pC2, pH1);

    // ---- GAT layer 2 ----
    gemm_tf32<0, true><<<dim3(M / 128, FF / 128), 256>>>(pH1, W2, nullptr, pWh, M, FF, FF);
    sc_kernel<<<M / 8, 256>>>(pWh, a2, pSc1, pSc2);
    colstats<<<dim3(NWORDS, Bb), 256>>>(pSc1, pSc2, pC2);
    agg_tf32<<<dim3(NN / 128, FF / 128, Bb), 256>>>(pWh, pSc1, pC2, pH2);

    // ---- residual + LN1 ----
    add_ln<<<M / 8, 256>>>(x, pH2, gln1, bln1, pHln);

    // ---- feed-forward (split-TF32 for fp32-level accuracy) ----
    gemm_tf32<1, true><<<dim3(M / 128, HH / 128), 256>>>(pHln, wff1, bff1, pMid, M, HH, FF);
    gemm_tf32<2, true><<<dim3(M / 128, FF / 128), 256>>>(pMid, wff2, bff2, pFFo, M, FF, HH);

    // ---- residual + LN2 -> output ----
    add_ln<<<M / 8, 256>>>(pHln, pFFo, gln2, bln2, out);
}

// round 14
// speedup vs baseline: 1.4439x; 1.4439x over previous
#include <cuda_runtime.h>
#include <cuda_bf16.h>
#include <cstdint>
#include <cstddef>

// Problem dims (fixed by the reference)
#define Bb 2
#define NN 4096
#define FF 256
#define HH 1024
#define NWORDS 128   // NN/32

// ---------------- scratch (device globals; no allocation allowed) ----------
__device__ __align__(16) uint32_t g_bits[Bb][NN][NWORDS];   // 4 MB adjacency bitmask
__device__ __align__(16) float g_Wh [Bb * NN * FF];         // current layer Wh
__device__ __align__(16) float g_h1 [Bb * NN * FF];         // GAT1 out
__device__ __align__(16) float g_h2 [Bb * NN * FF];         // GAT2 out
__device__ __align__(16) float g_hln[Bb * NN * FF];         // after LN1
__device__ __align__(16) float g_mid[Bb * NN * HH];         // FF hidden
__device__ __align__(16) float g_ff [Bb * NN * FF];         // FF out
__device__ __align__(16) float g_sc1[Bb * NN];
__device__ __align__(16) float g_sc2[Bb * NN];
__device__ __align__(16) float2 g_c2[Bb * NN];              // {sc2[j], c[j]}

// ---------------- helpers ---------------------------------------------------
__device__ __forceinline__ uint32_t f2tf(float x) {
    uint32_t u;
    asm("cvt.rna.tf32.f32 %0, %1;" : "=r"(u) : "f"(x));
    return u;
}

__device__ __forceinline__ void mma_tf32(float c[4],
        const uint32_t a[4], const uint32_t b[2]) {
    asm volatile(
        "mma.sync.aligned.m16n8k8.row.col.f32.tf32.tf32.f32 "
        "{%0,%1,%2,%3}, {%4,%5,%6,%7}, {%8,%9}, {%0,%1,%2,%3};\n"
        : "+f"(c[0]), "+f"(c[1]), "+f"(c[2]), "+f"(c[3])
        : "r"(a[0]), "r"(a[1]), "r"(a[2]), "r"(a[3]), "r"(b[0]), "r"(b[1]));
}

#define SAS 36    // sA row stride (floats): conflict-free A-frag loads
#define SBS 136   // sB row stride (floats): (r*136+g)%32 = r*8+g -> conflict-free

// ---------------- 1) pack adjacency into bitmask ----------------------------
__global__ void pack_bits(const int* __restrict__ adj) {
    // one block per (b,i) row; blockIdx.x = b*NN + i
    const int warp = threadIdx.x >> 5, lane = threadIdx.x & 31;
    const size_t base = (size_t)blockIdx.x * NN;
    uint32_t* gb = &g_bits[0][0][0];
    for (int t = warp; t < NWORDS; t += 8) {
        int j = t * 32 + lane;
        unsigned m = __ballot_sync(0xffffffffu, adj[base + j] > 0);
        if (lane == 0) gb[(size_t)blockIdx.x * NWORDS + t] = m;
    }
}

// ---------------- 2) per-row attention scalars sc1,sc2 ----------------------
__global__ __launch_bounds__(256)
void sc_kernel(const float* __restrict__ Wh, const float* __restrict__ a,
               float* __restrict__ sc1, float* __restrict__ sc2) {
    int row = blockIdx.x * 8 + (threadIdx.x >> 5);
    int lane = threadIdx.x & 31;
    const float* wp = Wh + (size_t)row * FF;
    float d1 = 0.f, d2 = 0.f;
#pragma unroll
    for (int q = 0; q < 8; q++) {
        int f = lane + q * 32;
        float wv = wp[f];
        d1 += wv * __ldg(&a[f]);
        d2 += wv * __ldg(&a[FF + f]);
    }
#pragma unroll
    for (int o = 16; o; o >>= 1) {
        d1 += __shfl_xor_sync(0xffffffffu, d1, o);
        d2 += __shfl_xor_sync(0xffffffffu, d2, o);
    }
    if (lane == 0) { sc1[row] = d1; sc2[row] = d2; }
}

// ---------------- 3) column softmax stats: c[j] = m[j] + log(colsum[j]) -----
// grid (NWORDS, Bb), 256 threads; warp w scans i in [w*512,(w+1)*512), lane=j bit
__global__ __launch_bounds__(256)
void colstats(const float* __restrict__ sc1, const float* __restrict__ sc2,
              float2* __restrict__ c2) {
    const int b = blockIdx.y, wi = blockIdx.x;
    const int w = threadIdx.x >> 5, lane = threadIdx.x & 31;
    __shared__ float s1[NN];
    __shared__ float red[8][32];
    for (int i = threadIdx.x; i < NN; i += 256) s1[i] = sc1[b * NN + i];
    __syncthreads();

    const uint32_t* bw = &g_bits[b][0][wi];   // stride NWORDS per row
    const uint32_t sel = 1u << lane;
    const int i0 = w * 512;

    float mx = -3.0e38f;
#pragma unroll 4
    for (int i = i0; i < i0 + 512; i++) {
        uint32_t wv = __ldg(&bw[(size_t)i * NWORDS]);
        if (wv & sel) mx = fmaxf(mx, s1[i]);
    }
    red[w][lane] = mx;
    __syncthreads();
    float gmx = red[0][lane];
#pragma unroll
    for (int k = 1; k < 8; k++) gmx = fmaxf(gmx, red[k][lane]);

    const int j = wi * 32 + lane;
    const float s2 = __ldg(&sc2[b * NN + j]);
    float u = gmx + s2;
    float mcol = u > 0.f ? u : 0.2f * u;           // lrelu(max) = max lrelu

    float sum = 0.f;
#pragma unroll 4
    for (int i = i0; i < i0 + 512; i++) {
        uint32_t wv = __ldg(&bw[(size_t)i * NWORDS]);
        if (wv & sel) {
            float t = s1[i] + s2;
            float s = t > 0.f ? t : 0.2f * t;
            sum += __expf(s - mcol);
        }
    }
    __syncthreads();
    red[w][lane] = sum;
    __syncthreads();
    if (w == 0) {
        float tot = 0.f;
#pragma unroll
        for (int k = 0; k < 8; k++) tot += red[k][lane];
        float c = (tot > 0.f) ? (mcol + __logf(tot)) : 0.f;
        c2[b * NN + j] = make_float2(s2, c);
    }
}

// ---------------- 4) generic TF32 GEMM: C = A[M,K] @ B[K,N] (+epilogue) -----
// EPI: 0 = none, 1 = bias+relu, 2 = bias.  SPLIT: hi/lo 3-mma fp32 emulation.
template<int EPI, bool SPLIT>
__global__ __launch_bounds__(256, 1)
void gemm_tf32(const float* __restrict__ A, const float* __restrict__ B,
               const float* __restrict__ bias, float* __restrict__ C,
               int M, int Ncols, int K) {
    __shared__ __align__(16) float sA[128 * SAS];
    __shared__ __align__(16) float sB[32 * SBS];
    const int tid = threadIdx.x;
    const int i0 = blockIdx.x * 128;
    const int n0 = blockIdx.y * 128;
    const int w = tid >> 5, lane = tid & 31;
    const int wm = w >> 2, wn = w & 3;
    const int g = lane >> 2, r = lane & 3;

    float acc[4][4][4];
#pragma unroll
    for (int a = 0; a < 4; a++)
#pragma unroll
        for (int bq = 0; bq < 4; bq++)
#pragma unroll
            for (int cq = 0; cq < 4; cq++) acc[a][bq][cq] = 0.f;

    for (int kt = 0; kt < K; kt += 32) {
#pragma unroll
        for (int t = 0; t < 4; t++) {
            int idx = tid + t * 256;
            int row = idx >> 3, c4 = (idx & 7) << 2;
            float4 v = *reinterpret_cast<const float4*>(
                &A[(size_t)(i0 + row) * K + kt + c4]);
            *reinterpret_cast<float4*>(&sA[row * SAS + c4]) = v;
        }
#pragma unroll
        for (int t = 0; t < 4; t++) {
            int idx = tid + t * 256;
            int row = idx >> 5, c4 = (idx & 31) << 2;
            float4 v = *reinterpret_cast<const float4*>(
                &B[(size_t)(kt + row) * Ncols + n0 + c4]);
            *reinterpret_cast<float4*>(&sB[row * SBS + c4]) = v;
        }
        __syncthreads();
#pragma unroll
        for (int kk = 0; kk < 4; kk++) {
            uint32_t ah[4][4], al[4][4], bh[4][2], bl[4][2];
#pragma unroll
            for (int mt = 0; mt < 4; mt++) {
                int base = wm * 64 + mt * 16;
                float v0 = sA[(base + g)     * SAS + kk * 8 + r];
                float v1 = sA[(base + g + 8) * SAS + kk * 8 + r];
                float v2 = sA[(base + g)     * SAS + kk * 8 + r + 4];
                float v3 = sA[(base + g + 8) * SAS + kk * 8 + r + 4];
                ah[mt][0] = f2tf(v0); ah[mt][1] = f2tf(v1);
                ah[mt][2] = f2tf(v2); ah[mt][3] = f2tf(v3);
                if (SPLIT) {
                    al[mt][0] = f2tf(v0 - __uint_as_float(ah[mt][0]));
                    al[mt][1] = f2tf(v1 - __uint_as_float(ah[mt][1]));
                    al[mt][2] = f2tf(v2 - __uint_as_float(ah[mt][2]));
                    al[mt][3] = f2tf(v3 - __uint_as_float(ah[mt][3]));
                }
            }
#pragma unroll
            for (int nt = 0; nt < 4; nt++) {
                int nb = wn * 32 + nt * 8 + g;
                float v0 = sB[(kk * 8 + r)     * SBS + nb];
                float v1 = sB[(kk * 8 + r + 4) * SBS + nb];
                bh[nt][0] = f2tf(v0); bh[nt][1] = f2tf(v1);
                if (SPLIT) {
                    bl[nt][0] = f2tf(v0 - __uint_as_float(bh[nt][0]));
                    bl[nt][1] = f2tf(v1 - __uint_as_float(bh[nt][1]));
                }
            }
#pragma unroll
            for (int mt = 0; mt < 4; mt++)
#pragma unroll
                for (int nt = 0; nt < 4; nt++) {
                    mma_tf32(acc[mt][nt], ah[mt], bh[nt]);
                    if (SPLIT) {
                        mma_tf32(acc[mt][nt], ah[mt], bl[nt]);
                        mma_tf32(acc[mt][nt], al[mt], bh[nt]);
                    }
                }
        }
        __syncthreads();
    }
#pragma unroll
    for (int mt = 0; mt < 4; mt++) {
#pragma unroll
        for (int nt = 0; nt < 4; nt++) {
            int row = i0 + wm * 64 + mt * 16 + g;
            int col = n0 + wn * 32 + nt * 8 + 2 * r;
            float b0 = 0.f, b1 = 0.f;
            if (EPI != 0) { b0 = __ldg(&bias[col]); b1 = __ldg(&bias[col + 1]); }
            float x0 = acc[mt][nt][0] + b0, x1 = acc[mt][nt][1] + b1;
            float x2 = acc[mt][nt][2] + b0, x3 = acc[mt][nt][3] + b1;
            if (EPI == 1) {
                x0 = fmaxf(x0, 0.f); x1 = fmaxf(x1, 0.f);
                x2 = fmaxf(x2, 0.f); x3 = fmaxf(x3, 0.f);
            }
            *reinterpret_cast<float2*>(&C[(size_t)row * Ncols + col]) =
                make_float2(x0, x1);
            *reinterpret_cast<float2*>(&C[(size_t)(row + 8) * Ncols + col]) =
                make_float2(x2, x3);
        }
    }
}

// ---------------- 5) aggregation: out = E @ Wh, E generated on the fly ------
// E[i,j] = adj(i,j) ? exp(lrelu(sc1[i]+sc2[j]) - c[j]) : 0
__global__ __launch_bounds__(256, 1)
void agg_tf32(const float* __restrict__ Wh, const float* __restrict__ sc1,
              const float2* __restrict__ c2, float* __restrict__ out) {
    __shared__ __align__(16) float sA[128 * SAS];
    __shared__ __align__(16) float sB[32 * SBS];
    __shared__ float s1[128];
    const int tid = threadIdx.x;
    const int b = blockIdx.z;
    const int i0 = blockIdx.x * 128;
    const int n0 = blockIdx.y * 128;
    const int w = tid >> 5, lane = tid & 31;
    const int wm = w >> 2, wn = w & 3;
    const int g = lane >> 2, r = lane & 3;

    if (tid < 128) s1[tid] = sc1[b * NN + i0 + tid];
    const float* WhB = Wh + (size_t)b * NN * FF;

    float acc[4][4][4];
#pragma unroll
    for (int a = 0; a < 4; a++)
#pragma unroll
        for (int bq = 0; bq < 4; bq++)
#pragma unroll
            for (int cq = 0; cq < 4; cq++) acc[a][bq][cq] = 0.f;
    __syncthreads();

    const int arow = tid >> 1;
    const int jl0  = (tid & 1) << 4;
    const float v1 = s1[arow];

    for (int kt = 0; kt < NN / 32; kt++) {
        const int j0 = kt * 32;
        // --- generate E tile [128 x 32] into sA (fp32) ---
        {
            uint32_t word = g_bits[b][i0 + arow][kt] >> jl0;
            float ev[16];
#pragma unroll
            for (int q = 0; q < 16; q++) {
                float e = 0.f;
                if ((word >> q) & 1u) {
                    float2 p = __ldg(&c2[b * NN + j0 + jl0 + q]);
                    float u = v1 + p.x;
                    float s = u > 0.f ? u : 0.2f * u;
                    e = __expf(s - p.y);
                }
                ev[q] = e;
            }
            float4* dst = reinterpret_cast<float4*>(&sA[arow * SAS + jl0]);
            dst[0] = make_float4(ev[0],  ev[1],  ev[2],  ev[3]);
            dst[1] = make_float4(ev[4],  ev[5],  ev[6],  ev[7]);
            dst[2] = make_float4(ev[8],  ev[9],  ev[10], ev[11]);
            dst[3] = make_float4(ev[12], ev[13], ev[14], ev[15]);
        }
        // --- load Wh tile [32 x 128] (L2-resident) ---
#pragma unroll
        for (int t = 0; t < 4; t++) {
            int idx = tid + t * 256;
            int row = idx >> 5, c4 = (idx & 31) << 2;
            float4 v = *reinterpret_cast<const float4*>(
                &WhB[(size_t)(j0 + row) * FF + n0 + c4]);
            *reinterpret_cast<float4*>(&sB[row * SBS + c4]) = v;
        }
        __syncthreads();
#pragma unroll
        for (int kk = 0; kk < 4; kk++) {
            uint32_t af[4][4], bf[4][2];
#pragma unroll
            for (int mt = 0; mt < 4; mt++) {
                int base = wm * 64 + mt * 16;
                af[mt][0] = f2tf(sA[(base + g)     * SAS + kk * 8 + r]);
                af[mt][1] = f2tf(sA[(base + g + 8) * SAS + kk * 8 + r]);
                af[mt][2] = f2tf(sA[(base + g)     * SAS + kk * 8 + r + 4]);
                af[mt][3] = f2tf(sA[(base + g + 8) * SAS + kk * 8 + r + 4]);
            }
#pragma unroll
            for (int nt = 0; nt < 4; nt++) {
                int nb = wn * 32 + nt * 8 + g;
                bf[nt][0] = f2tf(sB[(kk * 8 + r)     * SBS + nb]);
                bf[nt][1] = f2tf(sB[(kk * 8 + r + 4) * SBS + nb]);
            }
#pragma unroll
            for (int mt = 0; mt < 4; mt++)
#pragma unroll
                for (int nt = 0; nt < 4; nt++)
                    mma_tf32(acc[mt][nt], af[mt], bf[nt]);
        }
        __syncthreads();
    }
#pragma unroll
    for (int mt = 0; mt < 4; mt++) {
#pragma unroll
        for (int nt = 0; nt < 4; nt++) {
            int row = i0 + wm * 64 + mt * 16 + g;
            int col = n0 + wn * 32 + nt * 8 + 2 * r;
            size_t o0 = ((size_t)b * NN + row) * FF + col;
            *reinterpret_cast<float2*>(&out[o0]) =
                make_float2(acc[mt][nt][0], acc[mt][nt][1]);
            *reinterpret_cast<float2*>(&out[o0 + (size_t)8 * FF]) =
                make_float2(acc[mt][nt][2], acc[mt][nt][3]);
        }
    }
}

// ---------------- 6) residual + layernorm -----------------------------------
__global__ __launch_bounds__(256)
void add_ln(const float* __restrict__ resid, const float* __restrict__ h,
            const float* __restrict__ gam, const float* __restrict__ bet,
            float* __restrict__ out) {
    int row = blockIdx.x * 8 + (threadIdx.x >> 5);
    int lane = threadIdx.x & 31;
    const float* rp = resid + (size_t)row * FF;
    const float* hp = h + (size_t)row * FF;
    float v[8];
    float sum = 0.f, sq = 0.f;
#pragma unroll
    for (int q = 0; q < 8; q++) {
        float xv = rp[lane + q * 32] + hp[lane + q * 32];
        v[q] = xv; sum += xv; sq += xv * xv;
    }
#pragma unroll
    for (int o = 16; o; o >>= 1) {
        sum += __shfl_xor_sync(0xffffffffu, sum, o);
        sq  += __shfl_xor_sync(0xffffffffu, sq, o);
    }
    float mean = sum * (1.f / FF);
    float var = sq * (1.f / FF) - mean * mean;
    float rstd = rsqrtf(var + 1e-5f);
#pragma unroll
    for (int q = 0; q < 8; q++) {
        int f = lane + q * 32;
        out[(size_t)row * FF + f] = (v[q] - mean) * rstd * __ldg(&gam[f]) + __ldg(&bet[f]);
    }
}

// ---------------- host orchestration ----------------------------------------
extern "C" void kernel_launch(void* const* d_in, const int* in_sizes, int n_in,
                              void* d_out, int out_size) {
    const float* x    = (const float*)d_in[0];
    const int*   adj  = (const int*)  d_in[1];
    const float* W1   = (const float*)d_in[2];
    const float* a1   = (const float*)d_in[3];
    const float* W2   = (const float*)d_in[4];
    const float* a2   = (const float*)d_in[5];
    const float* wff1 = (const float*)d_in[6];
    const float* bff1 = (const float*)d_in[7];
    const float* wff2 = (const float*)d_in[8];
    const float* bff2 = (const float*)d_in[9];
    const float* gln1 = (const float*)d_in[10];
    const float* bln1 = (const float*)d_in[11];
    const float* gln2 = (const float*)d_in[12];
    const float* bln2 = (const float*)d_in[13];
    float* out = (float*)d_out;

    float *pWh, *pH1, *pH2, *pHln, *pMid, *pFFo, *pSc1, *pSc2;
    float2* pC2;
    cudaGetSymbolAddress((void**)&pWh,  g_Wh);
    cudaGetSymbolAddress((void**)&pH1,  g_h1);
    cudaGetSymbolAddress((void**)&pH2,  g_h2);
    cudaGetSymbolAddress((void**)&pHln, g_hln);
    cudaGetSymbolAddress((void**)&pMid, g_mid);
    cudaGetSymbolAddress((void**)&pFFo, g_ff);
    cudaGetSymbolAddress((void**)&pSc1, g_sc1);
    cudaGetSymbolAddress((void**)&pSc2, g_sc2);
    cudaGetSymbolAddress((void**)&pC2,  g_c2);

    const int M = Bb * NN;   // 8192

    pack_bits<<<Bb * NN, 256>>>(adj);

    // ---- GAT layer 1 ----
    gemm_tf32<0, true><<<dim3(M / 128, FF / 128), 256>>>(x, W1, nullptr, pWh, M, FF, FF);
    sc_kernel<<<M / 8, 256>>>(pWh, a1, pSc1, pSc2);
    colstats<<<dim3(NWORDS, Bb), 256>>>(pSc1, pSc2, pC2);
    agg_tf32<<<dim3(NN / 128, FF / 128, Bb), 256>>>(pWh, pSc1, pC2, pH1);

    // ---- GAT layer 2 ----
    gemm_tf32<0, true><<<dim3(M / 128, FF / 128), 256>>>(pH1, W2, nullptr, pWh, M, FF, FF);
    sc_kernel<<<M / 8, 256>>>(pWh, a2, pSc1, pSc2);
    colstats<<<dim3(NWORDS, Bb), 256>>>(pSc1, pSc2, pC2);
    agg_tf32<<<dim3(NN / 128, FF / 128, Bb), 256>>>(pWh, pSc1, pC2, pH2);

    // ---- residual + LN1 ----
    add_ln<<<M / 8, 256>>>(x, pH2, gln1, bln1, pHln);

    // ---- feed-forward (split-TF32 for fp32-level accuracy) ----
    gemm_tf32<1, true><<<dim3(M / 128, HH / 128), 256>>>(pHln, wff1, bff1, pMid, M, HH, FF);
    gemm_tf32<2, true><<<dim3(M / 128, FF / 128), 256>>>(pMid, wff2, bff2, pFFo, M, FF, HH);

    // ---- residual + LN2 -> output ----
    add_ln<<<M / 8, 256>>>(pHln, pFFo, gln2, bln2, out);
}

// round 15
// speedup vs baseline: 1.5690x; 1.0866x over previous
#include <cuda_runtime.h>
#include <cuda_bf16.h>
#include <cstdint>
#include <cstddef>

// Problem dims (fixed by the reference)
#define Bb 2
#define NN 4096
#define FF 256
#define HH 1024
#define NWORDS 128   // NN/32
#define NCHUNK 4     // i-chunks for colstats (1024 rows each)

// ---------------- scratch (device globals; no allocation allowed) ----------
__device__ __align__(16) uint32_t g_bits [Bb][NN][NWORDS];   // adj bitmask, row-major
__device__ __align__(16) uint32_t g_bitsT[Bb][NWORDS][NN];   // transposed: [i-word][j]
__device__ __align__(16) float g_Wh [Bb * NN * FF];
__device__ __align__(16) float g_h1 [Bb * NN * FF];
__device__ __align__(16) float g_h2 [Bb * NN * FF];
__device__ __align__(16) float g_hln[Bb * NN * FF];
__device__ __align__(16) float g_mid[Bb * NN * HH];
__device__ __align__(16) float g_ff [Bb * NN * FF];
__device__ __align__(16) float g_sc1[Bb * NN];
__device__ __align__(16) float g_sc2[Bb * NN];
__device__ __align__(16) float2 g_c2[Bb * NN];               // {sc2[j], c[j]}
__device__ __align__(16) float2 g_part[NCHUNK][Bb * NN];     // {m_chunk, sum_chunk}

// ---------------- helpers ---------------------------------------------------
__device__ __forceinline__ uint32_t f2tf(float x) {
    uint32_t u;
    asm("cvt.rna.tf32.f32 %0, %1;" : "=r"(u) : "f"(x));
    return u;
}

__device__ __forceinline__ void mma_tf32(float c[4],
        const uint32_t a[4], const uint32_t b[2]) {
    asm volatile(
        "mma.sync.aligned.m16n8k8.row.col.f32.tf32.tf32.f32 "
        "{%0,%1,%2,%3}, {%4,%5,%6,%7}, {%8,%9}, {%0,%1,%2,%3};\n"
        : "+f"(c[0]), "+f"(c[1]), "+f"(c[2]), "+f"(c[3])
        : "r"(a[0]), "r"(a[1]), "r"(a[2]), "r"(a[3]), "r"(b[0]), "r"(b[1]));
}

#define SAS 36    // sA row stride (floats): conflict-free A-frag loads
#define SBS 136   // sB row stride (floats): conflict-free B-frag loads

// ---------------- 1) pack adjacency into bitmask ----------------------------
__global__ void pack_bits(const int* __restrict__ adj) {
    const int warp = threadIdx.x >> 5, lane = threadIdx.x & 31;
    const size_t base = (size_t)blockIdx.x * NN;
    uint32_t* gb = &g_bits[0][0][0];
    for (int t = warp; t < NWORDS; t += 8) {
        int j = t * 32 + lane;
        unsigned m = __ballot_sync(0xffffffffu, adj[base + j] > 0);
        if (lane == 0) gb[(size_t)blockIdx.x * NWORDS + t] = m;
    }
}

// ---------------- 1b) bit-transpose: g_bitsT[b][iw][j] -----------------------
// warp handles a 32x32 bit tile via ballot
__global__ __launch_bounds__(256)
void transpose_bits() {
    const int warp = threadIdx.x >> 5, lane = threadIdx.x & 31;
    const int gw = blockIdx.x * 8 + warp;            // 512 blocks * 8 warps = 4096
    const int TILES = Bb * NWORDS * NWORDS;          // 32768
    for (int t = gw; t < TILES; t += 4096) {
        int b  = t >> 14;
        int iw = (t >> 7) & 127;
        int jw = t & 127;
        uint32_t w = g_bits[b][iw * 32 + lane][jw];
        uint32_t tw = 0;
#pragma unroll
        for (int q = 0; q < 32; q++) {
            uint32_t bq = __ballot_sync(0xffffffffu, (w >> q) & 1u);
            if (lane == q) tw = bq;
        }
        g_bitsT[b][iw][jw * 32 + lane] = tw;
    }
}

// ---------------- 2) per-row attention scalars sc1,sc2 ----------------------
__global__ __launch_bounds__(256)
void sc_kernel(const float* __restrict__ Wh, const float* __restrict__ a,
               float* __restrict__ sc1, float* __restrict__ sc2) {
    int row = blockIdx.x * 8 + (threadIdx.x >> 5);
    int lane = threadIdx.x & 31;
    const float* wp = Wh + (size_t)row * FF;
    float d1 = 0.f, d2 = 0.f;
#pragma unroll
    for (int q = 0; q < 8; q++) {
        int f = lane + q * 32;
        float wv = wp[f];
        d1 += wv * __ldg(&a[f]);
        d2 += wv * __ldg(&a[FF + f]);
    }
#pragma unroll
    for (int o = 16; o; o >>= 1) {
        d1 += __shfl_xor_sync(0xffffffffu, d1, o);
        d2 += __shfl_xor_sync(0xffffffffu, d2, o);
    }
    if (lane == 0) { sc1[row] = d1; sc2[row] = d2; }
}

// ---------------- 3a) partial column stats over an i-chunk -------------------
// grid (NN/256, NCHUNK, Bb), 256 threads. thread -> column j, chunk c.
// m_c = lrelu(max_{i in chunk, adj} sc1[i] + sc2[j]); s_c = sum exp(lrelu(.)-m_c)
__global__ __launch_bounds__(256)
void colstats_part(const float* __restrict__ sc1, const float* __restrict__ sc2) {
    const int b = blockIdx.z, c = blockIdx.y;
    const int j = blockIdx.x * 256 + threadIdx.x;
    __shared__ float s1c[1024];
    for (int i = threadIdx.x; i < 1024; i += 256)
        s1c[i] = sc1[b * NN + c * 1024 + i];
    __syncthreads();

    const uint32_t* T = &g_bitsT[b][c * 32][0];  // 32 words of i, stride NN per word

    // pass 1: max over adjacent i
    float mx = -3.0e38f;
#pragma unroll 4
    for (int k = 0; k < 32; k++) {
        uint32_t wv = __ldg(&T[(size_t)k * NN + j]);
#pragma unroll
        for (int q = 0; q < 32; q++)
            if ((wv >> q) & 1u) mx = fmaxf(mx, s1c[k * 32 + q]);
    }
    const float s2 = __ldg(&sc2[b * NN + j]);
    float u = mx + s2;
    float mloc = u > 0.f ? u : 0.2f * u;   // lrelu monotone -> commutes with max

    // pass 2: exp-sum relative to chunk max
    float sum = 0.f;
    if (mx > -1.0e38f) {
#pragma unroll 4
        for (int k = 0; k < 32; k++) {
            uint32_t wv = __ldg(&T[(size_t)k * NN + j]);
#pragma unroll
            for (int q = 0; q < 32; q++)
                if ((wv >> q) & 1u) {
                    float t = s1c[k * 32 + q] + s2;
                    float s = t > 0.f ? t : 0.2f * t;
                    sum += __expf(s - mloc);
                }
        }
    }
    g_part[c][b * NN + j] = make_float2(mloc, sum);
}

// ---------------- 3b) merge chunk stats -> c[j] ------------------------------
__global__ __launch_bounds__(256)
void colstats_reduce(const float* __restrict__ sc2, float2* __restrict__ c2) {
    const int t = blockIdx.x * 256 + threadIdx.x;   // t in [0, Bb*NN)
    float2 p[NCHUNK];
#pragma unroll
    for (int c = 0; c < NCHUNK; c++) p[c] = g_part[c][t];
    float m = -3.0e38f;
#pragma unroll
    for (int c = 0; c < NCHUNK; c++)
        if (p[c].y > 0.f) m = fmaxf(m, p[c].x);
    float s = 0.f;
#pragma unroll
    for (int c = 0; c < NCHUNK; c++)
        if (p[c].y > 0.f) s += p[c].y * __expf(p[c].x - m);
    float cc = (s > 0.f) ? (m + __logf(s)) : 0.f;
    c2[t] = make_float2(__ldg(&sc2[t]), cc);
}

// ---------------- 4) generic TF32 GEMM: C = A[M,K] @ B[K,N] (+epilogue) -----
// EPI: 0 = none, 1 = bias+relu, 2 = bias.  SPLIT: hi/lo 3-mma fp32 emulation.
template<int EPI, bool SPLIT>
__global__ __launch_bounds__(256, SPLIT ? 1 : 2)
void gemm_tf32(const float* __restrict__ A, const float* __restrict__ B,
               const float* __restrict__ bias, float* __restrict__ C,
               int M, int Ncols, int K) {
    __shared__ __align__(16) float sA[128 * SAS];
    __shared__ __align__(16) float sB[32 * SBS];
    const int tid = threadIdx.x;
    const int i0 = blockIdx.x * 128;
    const int n0 = blockIdx.y * 128;
    const int w = tid >> 5, lane = tid & 31;
    const int wm = w >> 2, wn = w & 3;
    const int g = lane >> 2, r = lane & 3;

    float acc[4][4][4];
#pragma unroll
    for (int a = 0; a < 4; a++)
#pragma unroll
        for (int bq = 0; bq < 4; bq++)
#pragma unroll
            for (int cq = 0; cq < 4; cq++) acc[a][bq][cq] = 0.f;

    for (int kt = 0; kt < K; kt += 32) {
#pragma unroll
        for (int t = 0; t < 4; t++) {
            int idx = tid + t * 256;
            int row = idx >> 3, c4 = (idx & 7) << 2;
            float4 v = *reinterpret_cast<const float4*>(
                &A[(size_t)(i0 + row) * K + kt + c4]);
            *reinterpret_cast<float4*>(&sA[row * SAS + c4]) = v;
        }
#pragma unroll
        for (int t = 0; t < 4; t++) {
            int idx = tid + t * 256;
            int row = idx >> 5, c4 = (idx & 31) << 2;
            float4 v = *reinterpret_cast<const float4*>(
                &B[(size_t)(kt + row) * Ncols + n0 + c4]);
            *reinterpret_cast<float4*>(&sB[row * SBS + c4]) = v;
        }
        __syncthreads();
#pragma unroll
        for (int kk = 0; kk < 4; kk++) {
            uint32_t ah[4][4], al[4][4], bh[4][2], bl[4][2];
#pragma unroll
            for (int mt = 0; mt < 4; mt++) {
                int base = wm * 64 + mt * 16;
                float v0 = sA[(base + g)     * SAS + kk * 8 + r];
                float v1 = sA[(base + g + 8) * SAS + kk * 8 + r];
                float v2 = sA[(base + g)     * SAS + kk * 8 + r + 4];
                float v3 = sA[(base + g + 8) * SAS + kk * 8 + r + 4];
                ah[mt][0] = f2tf(v0); ah[mt][1] = f2tf(v1);
                ah[mt][2] = f2tf(v2); ah[mt][3] = f2tf(v3);
                if (SPLIT) {
                    al[mt][0] = f2tf(v0 - __uint_as_float(ah[mt][0]));
                    al[mt][1] = f2tf(v1 - __uint_as_float(ah[mt][1]));
                    al[mt][2] = f2tf(v2 - __uint_as_float(ah[mt][2]));
                    al[mt][3] = f2tf(v3 - __uint_as_float(ah[mt][3]));
                }
            }
#pragma unroll
            for (int nt = 0; nt < 4; nt++) {
                int nb = wn * 32 + nt * 8 + g;
                float v0 = sB[(kk * 8 + r)     * SBS + nb];
                float v1 = sB[(kk * 8 + r + 4) * SBS + nb];
                bh[nt][0] = f2tf(v0); bh[nt][1] = f2tf(v1);
                if (SPLIT) {
                    bl[nt][0] = f2tf(v0 - __uint_as_float(bh[nt][0]));
                    bl[nt][1] = f2tf(v1 - __uint_as_float(bh[nt][1]));
                }
            }
#pragma unroll
            for (int mt = 0; mt < 4; mt++)
#pragma unroll
                for (int nt = 0; nt < 4; nt++) {
                    mma_tf32(acc[mt][nt], ah[mt], bh[nt]);
                    if (SPLIT) {
                        mma_tf32(acc[mt][nt], ah[mt], bl[nt]);
                        mma_tf32(acc[mt][nt], al[mt], bh[nt]);
                    }
                }
        }
        __syncthreads();
    }
#pragma unroll
    for (int mt = 0; mt < 4; mt++) {
#pragma unroll
        for (int nt = 0; nt < 4; nt++) {
            int row = i0 + wm * 64 + mt * 16 + g;
            int col = n0 + wn * 32 + nt * 8 + 2 * r;
            float b0 = 0.f, b1 = 0.f;
            if (EPI != 0) { b0 = __ldg(&bias[col]); b1 = __ldg(&bias[col + 1]); }
            float x0 = acc[mt][nt][0] + b0, x1 = acc[mt][nt][1] + b1;
            float x2 = acc[mt][nt][2] + b0, x3 = acc[mt][nt][3] + b1;
            if (EPI == 1) {
                x0 = fmaxf(x0, 0.f); x1 = fmaxf(x1, 0.f);
                x2 = fmaxf(x2, 0.f); x3 = fmaxf(x3, 0.f);
            }
            *reinterpret_cast<float2*>(&C[(size_t)row * Ncols + col]) =
                make_float2(x0, x1);
            *reinterpret_cast<float2*>(&C[(size_t)(row + 8) * Ncols + col]) =
                make_float2(x2, x3);
        }
    }
}

// ---------------- 5) aggregation: out = E @ Wh, E generated on the fly ------
// E[i,j] = adj(i,j) ? exp(lrelu(sc1[i]+sc2[j]) - c[j]) : 0
__global__ __launch_bounds__(256, 1)
void agg_tf32(const float* __restrict__ Wh, const float* __restrict__ sc1,
              const float2* __restrict__ c2, float* __restrict__ out) {
    __shared__ __align__(16) float sA[128 * SAS];
    __shared__ __align__(16) float sB[32 * SBS];
    __shared__ float s1[128];
    const int tid = threadIdx.x;
    const int b = blockIdx.z;
    const int i0 = blockIdx.x * 128;
    const int n0 = blockIdx.y * 128;
    const int w = tid >> 5, lane = tid & 31;
    const int wm = w >> 2, wn = w & 3;
    const int g = lane >> 2, r = lane & 3;

    if (tid < 128) s1[tid] = sc1[b * NN + i0 + tid];
    const float* WhB = Wh + (size_t)b * NN * FF;

    float acc[4][4][4];
#pragma unroll
    for (int a = 0; a < 4; a++)
#pragma unroll
        for (int bq = 0; bq < 4; bq++)
#pragma unroll
            for (int cq = 0; cq < 4; cq++) acc[a][bq][cq] = 0.f;
    __syncthreads();

    const int arow = tid >> 1;
    const int jl0  = (tid & 1) << 4;
    const float v1 = s1[arow];

    for (int kt = 0; kt < NN / 32; kt++) {
        const int j0 = kt * 32;
        // --- generate E tile [128 x 32] into sA (fp32) ---
        {
            uint32_t word = g_bits[b][i0 + arow][kt] >> jl0;
            float ev[16];
#pragma unroll
            for (int q = 0; q < 16; q++) {
                float e = 0.f;
                if ((word >> q) & 1u) {
                    float2 p = __ldg(&c2[b * NN + j0 + jl0 + q]);
                    float u = v1 + p.x;
                    float s = u > 0.f ? u : 0.2f * u;
                    e = __expf(s - p.y);
                }
                ev[q] = e;
            }
            float4* dst = reinterpret_cast<float4*>(&sA[arow * SAS + jl0]);
            dst[0] = make_float4(ev[0],  ev[1],  ev[2],  ev[3]);
            dst[1] = make_float4(ev[4],  ev[5],  ev[6],  ev[7]);
            dst[2] = make_float4(ev[8],  ev[9],  ev[10], ev[11]);
            dst[3] = make_float4(ev[12], ev[13], ev[14], ev[15]);
        }
        // --- load Wh tile [32 x 128] (L2-resident) ---
#pragma unroll
        for (int t = 0; t < 4; t++) {
            int idx = tid + t * 256;
            int row = idx >> 5, c4 = (idx & 31) << 2;
            float4 v = *reinterpret_cast<const float4*>(
                &WhB[(size_t)(j0 + row) * FF + n0 + c4]);
            *reinterpret_cast<float4*>(&sB[row * SBS + c4]) = v;
        }
        __syncthreads();
#pragma unroll
        for (int kk = 0; kk < 4; kk++) {
            uint32_t af[4][4], bf[4][2];
#pragma unroll
            for (int mt = 0; mt < 4; mt++) {
                int base = wm * 64 + mt * 16;
                af[mt][0] = f2tf(sA[(base + g)     * SAS + kk * 8 + r]);
                af[mt][1] = f2tf(sA[(base + g + 8) * SAS + kk * 8 + r]);
                af[mt][2] = f2tf(sA[(base + g)     * SAS + kk * 8 + r + 4]);
                af[mt][3] = f2tf(sA[(base + g + 8) * SAS + kk * 8 + r + 4]);
            }
#pragma unroll
            for (int nt = 0; nt < 4; nt++) {
                int nb = wn * 32 + nt * 8 + g;
                bf[nt][0] = f2tf(sB[(kk * 8 + r)     * SBS + nb]);
                bf[nt][1] = f2tf(sB[(kk * 8 + r + 4) * SBS + nb]);
            }
#pragma unroll
            for (int mt = 0; mt < 4; mt++)
#pragma unroll
                for (int nt = 0; nt < 4; nt++)
                    mma_tf32(acc[mt][nt], af[mt], bf[nt]);
        }
        __syncthreads();
    }
#pragma unroll
    for (int mt = 0; mt < 4; mt++) {
#pragma unroll
        for (int nt = 0; nt < 4; nt++) {
            int row = i0 + wm * 64 + mt * 16 + g;
            int col = n0 + wn * 32 + nt * 8 + 2 * r;
            size_t o0 = ((size_t)b * NN + row) * FF + col;
            *reinterpret_cast<float2*>(&out[o0]) =
                make_float2(acc[mt][nt][0], acc[mt][nt][1]);
            *reinterpret_cast<float2*>(&out[o0 + (size_t)8 * FF]) =
                make_float2(acc[mt][nt][2], acc[mt][nt][3]);
        }
    }
}

// ---------------- 6) residual + layernorm -----------------------------------
__global__ __launch_bounds__(256)
void add_ln(const float* __restrict__ resid, const float* __restrict__ h,
            const float* __restrict__ gam, const float* __restrict__ bet,
            float* __restrict__ out) {
    int row = blockIdx.x * 8 + (threadIdx.x >> 5);
    int lane = threadIdx.x & 31;
    const float* rp = resid + (size_t)row * FF;
    const float* hp = h + (size_t)row * FF;
    float v[8];
    float sum = 0.f, sq = 0.f;
#pragma unroll
    for (int q = 0; q < 8; q++) {
        float xv = rp[lane + q * 32] + hp[lane + q * 32];
        v[q] = xv; sum += xv; sq += xv * xv;
    }
#pragma unroll
    for (int o = 16; o; o >>= 1) {
        sum += __shfl_xor_sync(0xffffffffu, sum, o);
        sq  += __shfl_xor_sync(0xffffffffu, sq, o);
    }
    float mean = sum * (1.f / FF);
    float var = sq * (1.f / FF) - mean * mean;
    float rstd = rsqrtf(var + 1e-5f);
#pragma unroll
    for (int q = 0; q < 8; q++) {
        int f = lane + q * 32;
        out[(size_t)row * FF + f] = (v[q] - mean) * rstd * __ldg(&gam[f]) + __ldg(&bet[f]);
    }
}

// ---------------- host orchestration ----------------------------------------
extern "C" void kernel_launch(void* const* d_in, const int* in_sizes, int n_in,
                              void* d_out, int out_size) {
    const float* x    = (const float*)d_in[0];
    const int*   adj  = (const int*)  d_in[1];
    const float* W1   = (const float*)d_in[2];
    const float* a1   = (const float*)d_in[3];
    const float* W2   = (const float*)d_in[4];
    const float* a2   = (const float*)d_in[5];
    const float* wff1 = (const float*)d_in[6];
    const float* bff1 = (const float*)d_in[7];
    const float* wff2 = (const float*)d_in[8];
    const float* bff2 = (const float*)d_in[9];
    const float* gln1 = (const float*)d_in[10];
    const float* bln1 = (const float*)d_in[11];
    const float* gln2 = (const float*)d_in[12];
    const float* bln2 = (const float*)d_in[13];
    float* out = (float*)d_out;

    float *pWh, *pH1, *pH2, *pHln, *pMid, *pFFo, *pSc1, *pSc2;
    float2* pC2;
    cudaGetSymbolAddress((void**)&pWh,  g_Wh);
    cudaGetSymbolAddress((void**)&pH1,  g_h1);
    cudaGetSymbolAddress((void**)&pH2,  g_h2);
    cudaGetSymbolAddress((void**)&pHln, g_hln);
    cudaGetSymbolAddress((void**)&pMid, g_mid);
    cudaGetSymbolAddress((void**)&pFFo, g_ff);
    cudaGetSymbolAddress((void**)&pSc1, g_sc1);
    cudaGetSymbolAddress((void**)&pSc2, g_sc2);
    cudaGetSymbolAddress((void**)&pC2,  g_c2);

    const int M = Bb * NN;   // 8192

    pack_bits<<<Bb * NN, 256>>>(adj);
    transpose_bits<<<512, 256>>>();

    // ---- GAT layer 1 ----
    gemm_tf32<0, true><<<dim3(M / 128, FF / 128), 256>>>(x, W1, nullptr, pWh, M, FF, FF);
    sc_kernel<<<M / 8, 256>>>(pWh, a1, pSc1, pSc2);
    colstats_part<<<dim3(NN / 256, NCHUNK, Bb), 256>>>(pSc1, pSc2);
    colstats_reduce<<<(Bb * NN) / 256, 256>>>(pSc2, pC2);
    agg_tf32<<<dim3(NN / 128, FF / 128, Bb), 256>>>(pWh, pSc1, pC2, pH1);

    // ---- GAT layer 2 ----
    gemm_tf32<0, true><<<dim3(M / 128, FF / 128), 256>>>(pH1, W2, nullptr, pWh, M, FF, FF);
    sc_kernel<<<M / 8, 256>>>(pWh, a2, pSc1, pSc2);
    colstats_part<<<dim3(NN / 256, NCHUNK, Bb), 256>>>(pSc1, pSc2);
    colstats_reduce<<<(Bb * NN) / 256, 256>>>(pSc2, pC2);
    agg_tf32<<<dim3(NN / 128, FF / 128, Bb), 256>>>(pWh, pSc1, pC2, pH2);

    // ---- residual + LN1 ----
    add_ln<<<M / 8, 256>>>(x, pH2, gln1, bln1, pHln);

    // ---- feed-forward (plain TF32: error budget has 200x margin) ----
    gemm_tf32<1, false><<<dim3(M / 128, HH / 128), 256>>>(pHln, wff1, bff1, pMid, M, HH, FF);
    gemm_tf32<2, false><<<dim3(M / 128, FF / 128), 256>>>(pMid, wff2, bff2, pFFo, M, FF, HH);

    // ---- residual + LN2 -> output ----
    add_ln<<<M / 8, 256>>>(pHln, pFFo, gln2, bln2, out);
}

// round 16
// speedup vs baseline: 1.5696x; 1.0004x over previous
#include <cuda_runtime.h>
#include <cuda_bf16.h>
#include <cstdint>
#include <cstddef>

// Problem dims (fixed by the reference)
#define Bb 2
#define NN 4096
#define FF 256
#define HH 1024
#define NWORDS 128   // NN/32
#define NCHUNK 4     // i-chunks for colstats (1024 rows each)

// ---------------- scratch (device globals; no allocation allowed) ----------
__device__ __align__(16) uint32_t g_bits [Bb][NN][NWORDS];   // adj bitmask, row-major
__device__ __align__(16) uint32_t g_bitsT[Bb][NWORDS][NN];   // transposed: [i-word][j]
__device__ __align__(16) float g_Wh [Bb * NN * FF];
__device__ __align__(16) float g_h1 [Bb * NN * FF];
__device__ __align__(16) float g_h2 [Bb * NN * FF];
__device__ __align__(16) float g_hln[Bb * NN * FF];
__device__ __align__(16) float g_mid[Bb * NN * HH];
__device__ __align__(16) float g_ff [Bb * NN * FF];
__device__ __align__(16) float g_sc1[Bb * NN];
__device__ __align__(16) float g_sc2[Bb * NN];
__device__ __align__(16) float2 g_c2[Bb * NN];               // {sc2[j], c[j]}
__device__ __align__(16) float2 g_part[NCHUNK][Bb * NN];     // {m_chunk, sum_chunk}

// ---------------- helpers ---------------------------------------------------
__device__ __forceinline__ uint32_t f2tf(float x) {
    uint32_t u;
    asm("cvt.rna.tf32.f32 %0, %1;" : "=r"(u) : "f"(x));
    return u;
}

__device__ __forceinline__ void mma_tf32(float c[4],
        const uint32_t a[4], const uint32_t b[2]) {
    asm volatile(
        "mma.sync.aligned.m16n8k8.row.col.f32.tf32.tf32.f32 "
        "{%0,%1,%2,%3}, {%4,%5,%6,%7}, {%8,%9}, {%0,%1,%2,%3};\n"
        : "+f"(c[0]), "+f"(c[1]), "+f"(c[2]), "+f"(c[3])
        : "r"(a[0]), "r"(a[1]), "r"(a[2]), "r"(a[3]), "r"(b[0]), "r"(b[1]));
}

#define SAS 36    // sA row stride (floats): conflict-free A-frag loads
#define SBS 136   // sB row stride (floats): conflict-free B-frag loads

// ---------------- 1) pack adjacency into bitmask ----------------------------
__global__ void pack_bits(const int* __restrict__ adj) {
    const int warp = threadIdx.x >> 5, lane = threadIdx.x & 31;
    const size_t base = (size_t)blockIdx.x * NN;
    uint32_t* gb = &g_bits[0][0][0];
    for (int t = warp; t < NWORDS; t += 8) {
        int j = t * 32 + lane;
        unsigned m = __ballot_sync(0xffffffffu, adj[base + j] > 0);
        if (lane == 0) gb[(size_t)blockIdx.x * NWORDS + t] = m;
    }
}

// ---------------- 1b) bit-transpose: g_bitsT[b][iw][j] -----------------------
// warp handles a 32x32 bit tile via ballot
__global__ __launch_bounds__(256)
void transpose_bits() {
    const int warp = threadIdx.x >> 5, lane = threadIdx.x & 31;
    const int gw = blockIdx.x * 8 + warp;            // 512 blocks * 8 warps = 4096
    const int TILES = Bb * NWORDS * NWORDS;          // 32768
    for (int t = gw; t < TILES; t += 4096) {
        int b  = t >> 14;
        int iw = (t >> 7) & 127;
        int jw = t & 127;
        uint32_t w = g_bits[b][iw * 32 + lane][jw];
        uint32_t tw = 0;
#pragma unroll
        for (int q = 0; q < 32; q++) {
            uint32_t bq = __ballot_sync(0xffffffffu, (w >> q) & 1u);
            if (lane == q) tw = bq;
        }
        g_bitsT[b][iw][jw * 32 + lane] = tw;
    }
}

// ---------------- 2) per-row attention scalars sc1,sc2 ----------------------
__global__ __launch_bounds__(256)
void sc_kernel(const float* __restrict__ Wh, const float* __restrict__ a,
               float* __restrict__ sc1, float* __restrict__ sc2) {
    int row = blockIdx.x * 8 + (threadIdx.x >> 5);
    int lane = threadIdx.x & 31;
    const float* wp = Wh + (size_t)row * FF;
    float d1 = 0.f, d2 = 0.f;
#pragma unroll
    for (int q = 0; q < 8; q++) {
        int f = lane + q * 32;
        float wv = wp[f];
        d1 += wv * __ldg(&a[f]);
        d2 += wv * __ldg(&a[FF + f]);
    }
#pragma unroll
    for (int o = 16; o; o >>= 1) {
        d1 += __shfl_xor_sync(0xffffffffu, d1, o);
        d2 += __shfl_xor_sync(0xffffffffu, d2, o);
    }
    if (lane == 0) { sc1[row] = d1; sc2[row] = d2; }
}

// ---------------- 3a) partial column stats over an i-chunk -------------------
// grid (NN/256, NCHUNK, Bb), 256 threads. thread -> column j, chunk c.
// m_c = lrelu(max_{i in chunk, adj} sc1[i] + sc2[j]); s_c = sum exp(lrelu(.)-m_c)
__global__ __launch_bounds__(256)
void colstats_part(const float* __restrict__ sc1, const float* __restrict__ sc2) {
    const int b = blockIdx.z, c = blockIdx.y;
    const int j = blockIdx.x * 256 + threadIdx.x;
    __shared__ float s1c[1024];
    for (int i = threadIdx.x; i < 1024; i += 256)
        s1c[i] = sc1[b * NN + c * 1024 + i];
    __syncthreads();

    const uint32_t* T = &g_bitsT[b][c * 32][0];  // 32 words of i, stride NN per word

    // pass 1: max over adjacent i
    float mx = -3.0e38f;
#pragma unroll 4
    for (int k = 0; k < 32; k++) {
        uint32_t wv = __ldg(&T[(size_t)k * NN + j]);
#pragma unroll
        for (int q = 0; q < 32; q++)
            if ((wv >> q) & 1u) mx = fmaxf(mx, s1c[k * 32 + q]);
    }
    const float s2 = __ldg(&sc2[b * NN + j]);
    float u = mx + s2;
    float mloc = u > 0.f ? u : 0.2f * u;   // lrelu monotone -> commutes with max

    // pass 2: exp-sum relative to chunk max
    float sum = 0.f;
    if (mx > -1.0e38f) {
#pragma unroll 4
        for (int k = 0; k < 32; k++) {
            uint32_t wv = __ldg(&T[(size_t)k * NN + j]);
#pragma unroll
            for (int q = 0; q < 32; q++)
                if ((wv >> q) & 1u) {
                    float t = s1c[k * 32 + q] + s2;
                    float s = t > 0.f ? t : 0.2f * t;
                    sum += __expf(s - mloc);
                }
        }
    }
    g_part[c][b * NN + j] = make_float2(mloc, sum);
}

// ---------------- 3b) merge chunk stats -> c[j] ------------------------------
__global__ __launch_bounds__(256)
void colstats_reduce(const float* __restrict__ sc2, float2* __restrict__ c2) {
    const int t = blockIdx.x * 256 + threadIdx.x;   // t in [0, Bb*NN)
    float2 p[NCHUNK];
#pragma unroll
    for (int c = 0; c < NCHUNK; c++) p[c] = g_part[c][t];
    float m = -3.0e38f;
#pragma unroll
    for (int c = 0; c < NCHUNK; c++)
        if (p[c].y > 0.f) m = fmaxf(m, p[c].x);
    float s = 0.f;
#pragma unroll
    for (int c = 0; c < NCHUNK; c++)
        if (p[c].y > 0.f) s += p[c].y * __expf(p[c].x - m);
    float cc = (s > 0.f) ? (m + __logf(s)) : 0.f;
    c2[t] = make_float2(__ldg(&sc2[t]), cc);
}

// ---------------- 4) generic TF32 GEMM: C = A[M,K] @ B[K,N] (+epilogue) -----
// EPI: 0 = none, 1 = bias+relu, 2 = bias.  SPLIT: hi/lo 3-mma fp32 emulation.
template<int EPI, bool SPLIT>
__global__ __launch_bounds__(256, SPLIT ? 1 : 2)
void gemm_tf32(const float* __restrict__ A, const float* __restrict__ B,
               const float* __restrict__ bias, float* __restrict__ C,
               int M, int Ncols, int K) {
    __shared__ __align__(16) float sA[128 * SAS];
    __shared__ __align__(16) float sB[32 * SBS];
    const int tid = threadIdx.x;
    const int i0 = blockIdx.x * 128;
    const int n0 = blockIdx.y * 128;
    const int w = tid >> 5, lane = tid & 31;
    const int wm = w >> 2, wn = w & 3;
    const int g = lane >> 2, r = lane & 3;

    float acc[4][4][4];
#pragma unroll
    for (int a = 0; a < 4; a++)
#pragma unroll
        for (int bq = 0; bq < 4; bq++)
#pragma unroll
            for (int cq = 0; cq < 4; cq++) acc[a][bq][cq] = 0.f;

    for (int kt = 0; kt < K; kt += 32) {
#pragma unroll
        for (int t = 0; t < 4; t++) {
            int idx = tid + t * 256;
            int row = idx >> 3, c4 = (idx & 7) << 2;
            float4 v = *reinterpret_cast<const float4*>(
                &A[(size_t)(i0 + row) * K + kt + c4]);
            *reinterpret_cast<float4*>(&sA[row * SAS + c4]) = v;
        }
#pragma unroll
        for (int t = 0; t < 4; t++) {
            int idx = tid + t * 256;
            int row = idx >> 5, c4 = (idx & 31) << 2;
            float4 v = *reinterpret_cast<const float4*>(
                &B[(size_t)(kt + row) * Ncols + n0 + c4]);
            *reinterpret_cast<float4*>(&sB[row * SBS + c4]) = v;
        }
        __syncthreads();
#pragma unroll
        for (int kk = 0; kk < 4; kk++) {
            uint32_t ah[4][4], al[4][4], bh[4][2], bl[4][2];
#pragma unroll
            for (int mt = 0; mt < 4; mt++) {
                int base = wm * 64 + mt * 16;
                float v0 = sA[(base + g)     * SAS + kk * 8 + r];
                float v1 = sA[(base + g + 8) * SAS + kk * 8 + r];
                float v2 = sA[(base + g)     * SAS + kk * 8 + r + 4];
                float v3 = sA[(base + g + 8) * SAS + kk * 8 + r + 4];
                ah[mt][0] = f2tf(v0); ah[mt][1] = f2tf(v1);
                ah[mt][2] = f2tf(v2); ah[mt][3] = f2tf(v3);
                if (SPLIT) {
                    al[mt][0] = f2tf(v0 - __uint_as_float(ah[mt][0]));
                    al[mt][1] = f2tf(v1 - __uint_as_float(ah[mt][1]));
                    al[mt][2] = f2tf(v2 - __uint_as_float(ah[mt][2]));
                    al[mt][3] = f2tf(v3 - __uint_as_float(ah[mt][3]));
                }
            }
#pragma unroll
            for (int nt = 0; nt < 4; nt++) {
                int nb = wn * 32 + nt * 8 + g;
                float v0 = sB[(kk * 8 + r)     * SBS + nb];
                float v1 = sB[(kk * 8 + r + 4) * SBS + nb];
                bh[nt][0] = f2tf(v0); bh[nt][1] = f2tf(v1);
                if (SPLIT) {
                    bl[nt][0] = f2tf(v0 - __uint_as_float(bh[nt][0]));
                    bl[nt][1] = f2tf(v1 - __uint_as_float(bh[nt][1]));
                }
            }
#pragma unroll
            for (int mt = 0; mt < 4; mt++)
#pragma unroll
                for (int nt = 0; nt < 4; nt++) {
                    mma_tf32(acc[mt][nt], ah[mt], bh[nt]);
                    if (SPLIT) {
                        mma_tf32(acc[mt][nt], ah[mt], bl[nt]);
                        mma_tf32(acc[mt][nt], al[mt], bh[nt]);
                    }
                }
        }
        __syncthreads();
    }
#pragma unroll
    for (int mt = 0; mt < 4; mt++) {
#pragma unroll
        for (int nt = 0; nt < 4; nt++) {
            int row = i0 + wm * 64 + mt * 16 + g;
            int col = n0 + wn * 32 + nt * 8 + 2 * r;
            float b0 = 0.f, b1 = 0.f;
            if (EPI != 0) { b0 = __ldg(&bias[col]); b1 = __ldg(&bias[col + 1]); }
            float x0 = acc[mt][nt][0] + b0, x1 = acc[mt][nt][1] + b1;
            float x2 = acc[mt][nt][2] + b0, x3 = acc[mt][nt][3] + b1;
            if (EPI == 1) {
                x0 = fmaxf(x0, 0.f); x1 = fmaxf(x1, 0.f);
                x2 = fmaxf(x2, 0.f); x3 = fmaxf(x3, 0.f);
            }
            *reinterpret_cast<float2*>(&C[(size_t)row * Ncols + col]) =
                make_float2(x0, x1);
            *reinterpret_cast<float2*>(&C[(size_t)(row + 8) * Ncols + col]) =
                make_float2(x2, x3);
        }
    }
}

// ---------------- 5) aggregation: out = E @ Wh, E generated on the fly ------
// E[i,j] = adj(i,j) ? exp(lrelu(sc1[i]+sc2[j]) - c[j]) : 0
__global__ __launch_bounds__(256, 1)
void agg_tf32(const float* __restrict__ Wh, const float* __restrict__ sc1,
              const float2* __restrict__ c2, float* __restrict__ out) {
    __shared__ __align__(16) float sA[128 * SAS];
    __shared__ __align__(16) float sB[32 * SBS];
    __shared__ float s1[128];
    const int tid = threadIdx.x;
    const int b = blockIdx.z;
    const int i0 = blockIdx.x * 128;
    const int n0 = blockIdx.y * 128;
    const int w = tid >> 5, lane = tid & 31;
    const int wm = w >> 2, wn = w & 3;
    const int g = lane >> 2, r = lane & 3;

    if (tid < 128) s1[tid] = sc1[b * NN + i0 + tid];
    const float* WhB = Wh + (size_t)b * NN * FF;

    float acc[4][4][4];
#pragma unroll
    for (int a = 0; a < 4; a++)
#pragma unroll
        for (int bq = 0; bq < 4; bq++)
#pragma unroll
            for (int cq = 0; cq < 4; cq++) acc[a][bq][cq] = 0.f;
    __syncthreads();

    const int arow = tid >> 1;
    const int jl0  = (tid & 1) << 4;
    const float v1 = s1[arow];

    for (int kt = 0; kt < NN / 32; kt++) {
        const int j0 = kt * 32;
        // --- generate E tile [128 x 32] into sA (fp32) ---
        {
            uint32_t word = g_bits[b][i0 + arow][kt] >> jl0;
            float ev[16];
#pragma unroll
            for (int q = 0; q < 16; q++) {
                float e = 0.f;
                if ((word >> q) & 1u) {
                    float2 p = __ldg(&c2[b * NN + j0 + jl0 + q]);
                    float u = v1 + p.x;
                    float s = u > 0.f ? u : 0.2f * u;
                    e = __expf(s - p.y);
                }
                ev[q] = e;
            }
            float4* dst = reinterpret_cast<float4*>(&sA[arow * SAS + jl0]);
            dst[0] = make_float4(ev[0],  ev[1],  ev[2],  ev[3]);
            dst[1] = make_float4(ev[4],  ev[5],  ev[6],  ev[7]);
            dst[2] = make_float4(ev[8],  ev[9],  ev[10], ev[11]);
            dst[3] = make_float4(ev[12], ev[13], ev[14], ev[15]);
        }
        // --- load Wh tile [32 x 128] (L2-resident) ---
#pragma unroll
        for (int t = 0; t < 4; t++) {
            int idx = tid + t * 256;
            int row = idx >> 5, c4 = (idx & 31) << 2;
            float4 v = *reinterpret_cast<const float4*>(
                &WhB[(size_t)(j0 + row) * FF + n0 + c4]);
            *reinterpret_cast<float4*>(&sB[row * SBS + c4]) = v;
        }
        __syncthreads();
#pragma unroll
        for (int kk = 0; kk < 4; kk++) {
            uint32_t af[4][4], bf[4][2];
#pragma unroll
            for (int mt = 0; mt < 4; mt++) {
                int base = wm * 64 + mt * 16;
                af[mt][0] = f2tf(sA[(base + g)     * SAS + kk * 8 + r]);
                af[mt][1] = f2tf(sA[(base + g + 8) * SAS + kk * 8 + r]);
                af[mt][2] = f2tf(sA[(base + g)     * SAS + kk * 8 + r + 4]);
                af[mt][3] = f2tf(sA[(base + g + 8) * SAS + kk * 8 + r + 4]);
            }
#pragma unroll
            for (int nt = 0; nt < 4; nt++) {
                int nb = wn * 32 + nt * 8 + g;
                bf[nt][0] = f2tf(sB[(kk * 8 + r)     * SBS + nb]);
                bf[nt][1] = f2tf(sB[(kk * 8 + r + 4) * SBS + nb]);
            }
#pragma unroll
            for (int mt = 0; mt < 4; mt++)
#pragma unroll
                for (int nt = 0; nt < 4; nt++)
                    mma_tf32(acc[mt][nt], af[mt], bf[nt]);
        }
        __syncthreads();
    }
#pragma unroll
    for (int mt = 0; mt < 4; mt++) {
#pragma unroll
        for (int nt = 0; nt < 4; nt++) {
            int row = i0 + wm * 64 + mt * 16 + g;
            int col = n0 + wn * 32 + nt * 8 + 2 * r;
            size_t o0 = ((size_t)b * NN + row) * FF + col;
            *reinterpret_cast<float2*>(&out[o0]) =
                make_float2(acc[mt][nt][0], acc[mt][nt][1]);
            *reinterpret_cast<float2*>(&out[o0 + (size_t)8 * FF]) =
                make_float2(acc[mt][nt][2], acc[mt][nt][3]);
        }
    }
}

// ---------------- 6) residual + layernorm -----------------------------------
__global__ __launch_bounds__(256)
void add_ln(const float* __restrict__ resid, const float* __restrict__ h,
            const float* __restrict__ gam, const float* __restrict__ bet,
            float* __restrict__ out) {
    int row = blockIdx.x * 8 + (threadIdx.x >> 5);
    int lane = threadIdx.x & 31;
    const float* rp = resid + (size_t)row * FF;
    const float* hp = h + (size_t)row * FF;
    float v[8];
    float sum = 0.f, sq = 0.f;
#pragma unroll
    for (int q = 0; q < 8; q++) {
        float xv = rp[lane + q * 32] + hp[lane + q * 32];
        v[q] = xv; sum += xv; sq += xv * xv;
    }
#pragma unroll
    for (int o = 16; o; o >>= 1) {
        sum += __shfl_xor_sync(0xffffffffu, sum, o);
        sq  += __shfl_xor_sync(0xffffffffu, sq, o);
    }
    float mean = sum * (1.f / FF);
    float var = sq * (1.f / FF) - mean * mean;
    float rstd = rsqrtf(var + 1e-5f);
#pragma unroll
    for (int q = 0; q < 8; q++) {
        int f = lane + q * 32;
        out[(size_t)row * FF + f] = (v[q] - mean) * rstd * __ldg(&gam[f]) + __ldg(&bet[f]);
    }
}

// ---------------- host orchestration ----------------------------------------
extern "C" void kernel_launch(void* const* d_in, const int* in_sizes, int n_in,
                              void* d_out, int out_size) {
    const float* x    = (const float*)d_in[0];
    const int*   adj  = (const int*)  d_in[1];
    const float* W1   = (const float*)d_in[2];
    const float* a1   = (const float*)d_in[3];
    const float* W2   = (const float*)d_in[4];
    const float* a2   = (const float*)d_in[5];
    const float* wff1 = (const float*)d_in[6];
    const float* bff1 = (const float*)d_in[7];
    const float* wff2 = (const float*)d_in[8];
    const float* bff2 = (const float*)d_in[9];
    const float* gln1 = (const float*)d_in[10];
    const float* bln1 = (const float*)d_in[11];
    const float* gln2 = (const float*)d_in[12];
    const float* bln2 = (const float*)d_in[13];
    float* out = (float*)d_out;

    float *pWh, *pH1, *pH2, *pHln, *pMid, *pFFo, *pSc1, *pSc2;
    float2* pC2;
    cudaGetSymbolAddress((void**)&pWh,  g_Wh);
    cudaGetSymbolAddress((void**)&pH1,  g_h1);
    cudaGetSymbolAddress((void**)&pH2,  g_h2);
    cudaGetSymbolAddress((void**)&pHln, g_hln);
    cudaGetSymbolAddress((void**)&pMid, g_mid);
    cudaGetSymbolAddress((void**)&pFFo, g_ff);
    cudaGetSymbolAddress((void**)&pSc1, g_sc1);
    cudaGetSymbolAddress((void**)&pSc2, g_sc2);
    cudaGetSymbolAddress((void**)&pC2,  g_c2);

    const int M = Bb * NN;   // 8192

    pack_bits<<<Bb * NN, 256>>>(adj);
    transpose_bits<<<512, 256>>>();

    // ---- GAT layer 1 ----
    gemm_tf32<0, true><<<dim3(M / 128, FF / 128), 256>>>(x, W1, nullptr, pWh, M, FF, FF);
    sc_kernel<<<M / 8, 256>>>(pWh, a1, pSc1, pSc2);
    colstats_part<<<dim3(NN / 256, NCHUNK, Bb), 256>>>(pSc1, pSc2);
    colstats_reduce<<<(Bb * NN) / 256, 256>>>(pSc2, pC2);
    agg_tf32<<<dim3(NN / 128, FF / 128, Bb), 256>>>(pWh, pSc1, pC2, pH1);

    // ---- GAT layer 2 ----
    gemm_tf32<0, true><<<dim3(M / 128, FF / 128), 256>>>(pH1, W2, nullptr, pWh, M, FF, FF);
    sc_kernel<<<M / 8, 256>>>(pWh, a2, pSc1, pSc2);
    colstats_part<<<dim3(NN / 256, NCHUNK, Bb), 256>>>(pSc1, pSc2);
    colstats_reduce<<<(Bb * NN) / 256, 256>>>(pSc2, pC2);
    agg_tf32<<<dim3(NN / 128, FF / 128, Bb), 256>>>(pWh, pSc1, pC2, pH2);

    // ---- residual + LN1 ----
    add_ln<<<M / 8, 256>>>(x, pH2, gln1, bln1, pHln);

    // ---- feed-forward (plain TF32: error budget has 200x margin) ----
    gemm_tf32<1, false><<<dim3(M / 128, HH / 128), 256>>>(pHln, wff1, bff1, pMid, M, HH, FF);
    gemm_tf32<2, false><<<dim3(M / 128, FF / 128), 256>>>(pMid, wff2, bff2, pFFo, M, FF, HH);

    // ---- residual + LN2 -> output ----
    add_ln<<<M / 8, 256>>>(pHln, pFFo, gln2, bln2, out);
}

// round 17
// speedup vs baseline: 1.5700x; 1.0002x over previous
#include <cuda_runtime.h>
#include <cuda_bf16.h>
#include <cstdint>
#include <cstddef>

// Problem dims (fixed by the reference)
#define Bb 2
#define NN 4096
#define FF 256
#define HH 1024
#define NWORDS 128   // NN/32
#define NCHUNK 4     // i-chunks for colstats (1024 rows each)

// ---------------- scratch (device globals; no allocation allowed) ----------
__device__ __align__(16) uint32_t g_bits [Bb][NN][NWORDS];   // adj bitmask, row-major
__device__ __align__(16) uint32_t g_bitsT[Bb][NWORDS][NN];   // transposed: [i-word][j]
__device__ __align__(16) float g_Wh [Bb * NN * FF];
__device__ __align__(16) float g_h1 [Bb * NN * FF];
__device__ __align__(16) float g_h2 [Bb * NN * FF];
__device__ __align__(16) float g_hln[Bb * NN * FF];
__device__ __align__(16) float g_mid[Bb * NN * HH];
__device__ __align__(16) float g_ff [Bb * NN * FF];
__device__ __align__(16) float g_sc1[Bb * NN];
__device__ __align__(16) float g_sc2[Bb * NN];
__device__ __align__(16) float2 g_c2[Bb * NN];               // {sc2[j], c[j]}
__device__ __align__(16) float2 g_part[NCHUNK][Bb * NN];     // {m_chunk, sum_chunk}

// ---------------- helpers ---------------------------------------------------
__device__ __forceinline__ uint32_t f2tf(float x) {
    uint32_t u;
    asm("cvt.rna.tf32.f32 %0, %1;" : "=r"(u) : "f"(x));
    return u;
}

__device__ __forceinline__ void mma_tf32(float c[4],
        const uint32_t a[4], const uint32_t b[2]) {
    asm volatile(
        "mma.sync.aligned.m16n8k8.row.col.f32.tf32.tf32.f32 "
        "{%0,%1,%2,%3}, {%4,%5,%6,%7}, {%8,%9}, {%0,%1,%2,%3};\n"
        : "+f"(c[0]), "+f"(c[1]), "+f"(c[2]), "+f"(c[3])
        : "r"(a[0]), "r"(a[1]), "r"(a[2]), "r"(a[3]), "r"(b[0]), "r"(b[1]));
}

#define SAS 36    // sA row stride (floats): conflict-free A-frag loads
#define SBS 136   // sB row stride (floats): conflict-free B-frag loads

// ---------------- 1) pack adjacency into bitmask ----------------------------
__global__ void pack_bits(const int* __restrict__ adj) {
    const int warp = threadIdx.x >> 5, lane = threadIdx.x & 31;
    const size_t base = (size_t)blockIdx.x * NN;
    uint32_t* gb = &g_bits[0][0][0];
    for (int t = warp; t < NWORDS; t += 8) {
        int j = t * 32 + lane;
        unsigned m = __ballot_sync(0xffffffffu, adj[base + j] > 0);
        if (lane == 0) gb[(size_t)blockIdx.x * NWORDS + t] = m;
    }
}

// ---------------- 1b) bit-transpose: g_bitsT[b][iw][j] -----------------------
// warp handles a 32x32 bit tile via ballot
__global__ __launch_bounds__(256)
void transpose_bits() {
    const int warp = threadIdx.x >> 5, lane = threadIdx.x & 31;
    const int gw = blockIdx.x * 8 + warp;            // 512 blocks * 8 warps = 4096
    const int TILES = Bb * NWORDS * NWORDS;          // 32768
    for (int t = gw; t < TILES; t += 4096) {
        int b  = t >> 14;
        int iw = (t >> 7) & 127;
        int jw = t & 127;
        uint32_t w = g_bits[b][iw * 32 + lane][jw];
        uint32_t tw = 0;
#pragma unroll
        for (int q = 0; q < 32; q++) {
            uint32_t bq = __ballot_sync(0xffffffffu, (w >> q) & 1u);
            if (lane == q) tw = bq;
        }
        g_bitsT[b][iw][jw * 32 + lane] = tw;
    }
}

// ---------------- 2) per-row attention scalars sc1,sc2 ----------------------
__global__ __launch_bounds__(256)
void sc_kernel(const float* __restrict__ Wh, const float* __restrict__ a,
               float* __restrict__ sc1, float* __restrict__ sc2) {
    int row = blockIdx.x * 8 + (threadIdx.x >> 5);
    int lane = threadIdx.x & 31;
    const float* wp = Wh + (size_t)row * FF;
    float d1 = 0.f, d2 = 0.f;
#pragma unroll
    for (int q = 0; q < 8; q++) {
        int f = lane + q * 32;
        float wv = wp[f];
        d1 += wv * __ldg(&a[f]);
        d2 += wv * __ldg(&a[FF + f]);
    }
#pragma unroll
    for (int o = 16; o; o >>= 1) {
        d1 += __shfl_xor_sync(0xffffffffu, d1, o);
        d2 += __shfl_xor_sync(0xffffffffu, d2, o);
    }
    if (lane == 0) { sc1[row] = d1; sc2[row] = d2; }
}

// ---------------- 3a) partial column stats over an i-chunk -------------------
// grid (NN/256, NCHUNK, Bb), 256 threads. thread -> column j, chunk c.
// m_c = lrelu(max_{i in chunk, adj} sc1[i] + sc2[j]); s_c = sum exp(lrelu(.)-m_c)
__global__ __launch_bounds__(256)
void colstats_part(const float* __restrict__ sc1, const float* __restrict__ sc2) {
    const int b = blockIdx.z, c = blockIdx.y;
    const int j = blockIdx.x * 256 + threadIdx.x;
    __shared__ float s1c[1024];
    for (int i = threadIdx.x; i < 1024; i += 256)
        s1c[i] = sc1[b * NN + c * 1024 + i];
    __syncthreads();

    const uint32_t* T = &g_bitsT[b][c * 32][0];  // 32 words of i, stride NN per word

    // pass 1: max over adjacent i
    float mx = -3.0e38f;
#pragma unroll 4
    for (int k = 0; k < 32; k++) {
        uint32_t wv = __ldg(&T[(size_t)k * NN + j]);
#pragma unroll
        for (int q = 0; q < 32; q++)
            if ((wv >> q) & 1u) mx = fmaxf(mx, s1c[k * 32 + q]);
    }
    const float s2 = __ldg(&sc2[b * NN + j]);
    float u = mx + s2;
    float mloc = u > 0.f ? u : 0.2f * u;   // lrelu monotone -> commutes with max

    // pass 2: exp-sum relative to chunk max
    float sum = 0.f;
    if (mx > -1.0e38f) {
#pragma unroll 4
        for (int k = 0; k < 32; k++) {
            uint32_t wv = __ldg(&T[(size_t)k * NN + j]);
#pragma unroll
            for (int q = 0; q < 32; q++)
                if ((wv >> q) & 1u) {
                    float t = s1c[k * 32 + q] + s2;
                    float s = t > 0.f ? t : 0.2f * t;
                    sum += __expf(s - mloc);
                }
        }
    }
    g_part[c][b * NN + j] = make_float2(mloc, sum);
}

// ---------------- 3b) merge chunk stats -> c[j] ------------------------------
__global__ __launch_bounds__(256)
void colstats_reduce(const float* __restrict__ sc2, float2* __restrict__ c2) {
    const int t = blockIdx.x * 256 + threadIdx.x;   // t in [0, Bb*NN)
    float2 p[NCHUNK];
#pragma unroll
    for (int c = 0; c < NCHUNK; c++) p[c] = g_part[c][t];
    float m = -3.0e38f;
#pragma unroll
    for (int c = 0; c < NCHUNK; c++)
        if (p[c].y > 0.f) m = fmaxf(m, p[c].x);
    float s = 0.f;
#pragma unroll
    for (int c = 0; c < NCHUNK; c++)
        if (p[c].y > 0.f) s += p[c].y * __expf(p[c].x - m);
    float cc = (s > 0.f) ? (m + __logf(s)) : 0.f;
    c2[t] = make_float2(__ldg(&sc2[t]), cc);
}

// ---------------- 4) generic TF32 GEMM: C = A[M,K] @ B[K,N] (+epilogue) -----
// EPI: 0 = none, 1 = bias+relu, 2 = bias.  SPLIT: hi/lo 3-mma fp32 emulation.
template<int EPI, bool SPLIT>
__global__ __launch_bounds__(256, SPLIT ? 1 : 2)
void gemm_tf32(const float* __restrict__ A, const float* __restrict__ B,
               const float* __restrict__ bias, float* __restrict__ C,
               int M, int Ncols, int K) {
    __shared__ __align__(16) float sA[128 * SAS];
    __shared__ __align__(16) float sB[32 * SBS];
    const int tid = threadIdx.x;
    const int i0 = blockIdx.x * 128;
    const int n0 = blockIdx.y * 128;
    const int w = tid >> 5, lane = tid & 31;
    const int wm = w >> 2, wn = w & 3;
    const int g = lane >> 2, r = lane & 3;

    float acc[4][4][4];
#pragma unroll
    for (int a = 0; a < 4; a++)
#pragma unroll
        for (int bq = 0; bq < 4; bq++)
#pragma unroll
            for (int cq = 0; cq < 4; cq++) acc[a][bq][cq] = 0.f;

    for (int kt = 0; kt < K; kt += 32) {
#pragma unroll
        for (int t = 0; t < 4; t++) {
            int idx = tid + t * 256;
            int row = idx >> 3, c4 = (idx & 7) << 2;
            float4 v = *reinterpret_cast<const float4*>(
                &A[(size_t)(i0 + row) * K + kt + c4]);
            *reinterpret_cast<float4*>(&sA[row * SAS + c4]) = v;
        }
#pragma unroll
        for (int t = 0; t < 4; t++) {
            int idx = tid + t * 256;
            int row = idx >> 5, c4 = (idx & 31) << 2;
            float4 v = *reinterpret_cast<const float4*>(
                &B[(size_t)(kt + row) * Ncols + n0 + c4]);
            *reinterpret_cast<float4*>(&sB[row * SBS + c4]) = v;
        }
        __syncthreads();
#pragma unroll
        for (int kk = 0; kk < 4; kk++) {
            uint32_t ah[4][4], al[4][4], bh[4][2], bl[4][2];
#pragma unroll
            for (int mt = 0; mt < 4; mt++) {
                int base = wm * 64 + mt * 16;
                float v0 = sA[(base + g)     * SAS + kk * 8 + r];
                float v1 = sA[(base + g + 8) * SAS + kk * 8 + r];
                float v2 = sA[(base + g)     * SAS + kk * 8 + r + 4];
                float v3 = sA[(base + g + 8) * SAS + kk * 8 + r + 4];
                ah[mt][0] = f2tf(v0); ah[mt][1] = f2tf(v1);
                ah[mt][2] = f2tf(v2); ah[mt][3] = f2tf(v3);
                if (SPLIT) {
                    al[mt][0] = f2tf(v0 - __uint_as_float(ah[mt][0]));
                    al[mt][1] = f2tf(v1 - __uint_as_float(ah[mt][1]));
                    al[mt][2] = f2tf(v2 - __uint_as_float(ah[mt][2]));
                    al[mt][3] = f2tf(v3 - __uint_as_float(ah[mt][3]));
                }
            }
#pragma unroll
            for (int nt = 0; nt < 4; nt++) {
                int nb = wn * 32 + nt * 8 + g;
                float v0 = sB[(kk * 8 + r)     * SBS + nb];
                float v1 = sB[(kk * 8 + r + 4) * SBS + nb];
                bh[nt][0] = f2tf(v0); bh[nt][1] = f2tf(v1);
                if (SPLIT) {
                    bl[nt][0] = f2tf(v0 - __uint_as_float(bh[nt][0]));
                    bl[nt][1] = f2tf(v1 - __uint_as_float(bh[nt][1]));
                }
            }
#pragma unroll
            for (int mt = 0; mt < 4; mt++)
#pragma unroll
                for (int nt = 0; nt < 4; nt++) {
                    mma_tf32(acc[mt][nt], ah[mt], bh[nt]);
                    if (SPLIT) {
                        mma_tf32(acc[mt][nt], ah[mt], bl[nt]);
                        mma_tf32(acc[mt][nt], al[mt], bh[nt]);
                    }
                }
        }
        __syncthreads();
    }
#pragma unroll
    for (int mt = 0; mt < 4; mt++) {
#pragma unroll
        for (int nt = 0; nt < 4; nt++) {
            int row = i0 + wm * 64 + mt * 16 + g;
            int col = n0 + wn * 32 + nt * 8 + 2 * r;
            float b0 = 0.f, b1 = 0.f;
            if (EPI != 0) { b0 = __ldg(&bias[col]); b1 = __ldg(&bias[col + 1]); }
            float x0 = acc[mt][nt][0] + b0, x1 = acc[mt][nt][1] + b1;
            float x2 = acc[mt][nt][2] + b0, x3 = acc[mt][nt][3] + b1;
            if (EPI == 1) {
                x0 = fmaxf(x0, 0.f); x1 = fmaxf(x1, 0.f);
                x2 = fmaxf(x2, 0.f); x3 = fmaxf(x3, 0.f);
            }
            *reinterpret_cast<float2*>(&C[(size_t)row * Ncols + col]) =
                make_float2(x0, x1);
            *reinterpret_cast<float2*>(&C[(size_t)(row + 8) * Ncols + col]) =
                make_float2(x2, x3);
        }
    }
}

// ---------------- 5) aggregation: out = E @ Wh, E generated on the fly ------
// E[i,j] = adj(i,j) ? exp(lrelu(sc1[i]+sc2[j]) - c[j]) : 0
__global__ __launch_bounds__(256, 1)
void agg_tf32(const float* __restrict__ Wh, const float* __restrict__ sc1,
              const float2* __restrict__ c2, float* __restrict__ out) {
    __shared__ __align__(16) float sA[128 * SAS];
    __shared__ __align__(16) float sB[32 * SBS];
    __shared__ float s1[128];
    const int tid = threadIdx.x;
    const int b = blockIdx.z;
    const int i0 = blockIdx.x * 128;
    const int n0 = blockIdx.y * 128;
    const int w = tid >> 5, lane = tid & 31;
    const int wm = w >> 2, wn = w & 3;
    const int g = lane >> 2, r = lane & 3;

    if (tid < 128) s1[tid] = sc1[b * NN + i0 + tid];
    const float* WhB = Wh + (size_t)b * NN * FF;

    float acc[4][4][4];
#pragma unroll
    for (int a = 0; a < 4; a++)
#pragma unroll
        for (int bq = 0; bq < 4; bq++)
#pragma unroll
            for (int cq = 0; cq < 4; cq++) acc[a][bq][cq] = 0.f;
    __syncthreads();

    const int arow = tid >> 1;
    const int jl0  = (tid & 1) << 4;
    const float v1 = s1[arow];

    for (int kt = 0; kt < NN / 32; kt++) {
        const int j0 = kt * 32;
        // --- generate E tile [128 x 32] into sA (fp32) ---
        {
            uint32_t word = g_bits[b][i0 + arow][kt] >> jl0;
            float ev[16];
#pragma unroll
            for (int q = 0; q < 16; q++) {
                float e = 0.f;
                if ((word >> q) & 1u) {
                    float2 p = __ldg(&c2[b * NN + j0 + jl0 + q]);
                    float u = v1 + p.x;
                    float s = u > 0.f ? u : 0.2f * u;
                    e = __expf(s - p.y);
                }
                ev[q] = e;
            }
            float4* dst = reinterpret_cast<float4*>(&sA[arow * SAS + jl0]);
            dst[0] = make_float4(ev[0],  ev[1],  ev[2],  ev[3]);
            dst[1] = make_float4(ev[4],  ev[5],  ev[6],  ev[7]);
            dst[2] = make_float4(ev[8],  ev[9],  ev[10], ev[11]);
            dst[3] = make_float4(ev[12], ev[13], ev[14], ev[15]);
        }
        // --- load Wh tile [32 x 128] (L2-resident) ---
#pragma unroll
        for (int t = 0; t < 4; t++) {
            int idx = tid + t * 256;
            int row = idx >> 5, c4 = (idx & 31) << 2;
            float4 v = *reinterpret_cast<const float4*>(
                &WhB[(size_t)(j0 + row) * FF + n0 + c4]);
            *reinterpret_cast<float4*>(&sB[row * SBS + c4]) = v;
        }
        __syncthreads();
#pragma unroll
        for (int kk = 0; kk < 4; kk++) {
            uint32_t af[4][4], bf[4][2];
#pragma unroll
            for (int mt = 0; mt < 4; mt++) {
                int base = wm * 64 + mt * 16;
                af[mt][0] = f2tf(sA[(base + g)     * SAS + kk * 8 + r]);
                af[mt][1] = f2tf(sA[(base + g + 8) * SAS + kk * 8 + r]);
                af[mt][2] = f2tf(sA[(base + g)     * SAS + kk * 8 + r + 4]);
                af[mt][3] = f2tf(sA[(base + g + 8) * SAS + kk * 8 + r + 4]);
            }
#pragma unroll
            for (int nt = 0; nt < 4; nt++) {
                int nb = wn * 32 + nt * 8 + g;
                bf[nt][0] = f2tf(sB[(kk * 8 + r)     * SBS + nb]);
                bf[nt][1] = f2tf(sB[(kk * 8 + r + 4) * SBS + nb]);
            }
#pragma unroll
            for (int mt = 0; mt < 4; mt++)
#pragma unroll
                for (int nt = 0; nt < 4; nt++)
                    mma_tf32(acc[mt][nt], af[mt], bf[nt]);
        }
        __syncthreads();
    }
#pragma unroll
    for (int mt = 0; mt < 4; mt++) {
#pragma unroll
        for (int nt = 0; nt < 4; nt++) {
            int row = i0 + wm * 64 + mt * 16 + g;
            int col = n0 + wn * 32 + nt * 8 + 2 * r;
            size_t o0 = ((size_t)b * NN + row) * FF + col;
            *reinterpret_cast<float2*>(&out[o0]) =
                make_float2(acc[mt][nt][0], acc[mt][nt][1]);
            *reinterpret_cast<float2*>(&out[o0 + (size_t)8 * FF]) =
                make_float2(acc[mt][nt][2], acc[mt][nt][3]);
        }
    }
}

// ---------------- 6) residual + layernorm -----------------------------------
__global__ __launch_bounds__(256)
void add_ln(const float* __restrict__ resid, const float* __restrict__ h,
            const float* __restrict__ gam, const float* __restrict__ bet,
            float* __restrict__ out) {
    int row = blockIdx.x * 8 + (threadIdx.x >> 5);
    int lane = threadIdx.x & 31;
    const float* rp = resid + (size_t)row * FF;
    const float* hp = h + (size_t)row * FF;
    float v[8];
    float sum = 0.f, sq = 0.f;
#pragma unroll
    for (int q = 0; q < 8; q++) {
        float xv = rp[lane + q * 32] + hp[lane + q * 32];
        v[q] = xv; sum += xv; sq += xv * xv;
    }
#pragma unroll
    for (int o = 16; o; o >>= 1) {
        sum += __shfl_xor_sync(0xffffffffu, sum, o);
        sq  += __shfl_xor_sync(0xffffffffu, sq, o);
    }
    float mean = sum * (1.f / FF);
    float var = sq * (1.f / FF) - mean * mean;
    float rstd = rsqrtf(var + 1e-5f);
#pragma unroll
    for (int q = 0; q < 8; q++) {
        int f = lane + q * 32;
        out[(size_t)row * FF + f] = (v[q] - mean) * rstd * __ldg(&gam[f]) + __ldg(&bet[f]);
    }
}

// ---------------- host orchestration ----------------------------------------
extern "C" void kernel_launch(void* const* d_in, const int* in_sizes, int n_in,
                              void* d_out, int out_size) {
    const float* x    = (const float*)d_in[0];
    const int*   adj  = (const int*)  d_in[1];
    const float* W1   = (const float*)d_in[2];
    const float* a1   = (const float*)d_in[3];
    const float* W2   = (const float*)d_in[4];
    const float* a2   = (const float*)d_in[5];
    const float* wff1 = (const float*)d_in[6];
    const float* bff1 = (const float*)d_in[7];
    const float* wff2 = (const float*)d_in[8];
    const float* bff2 = (const float*)d_in[9];
    const float* gln1 = (const float*)d_in[10];
    const float* bln1 = (const float*)d_in[11];
    const float* gln2 = (const float*)d_in[12];
    const float* bln2 = (const float*)d_in[13];
    float* out = (float*)d_out;

    float *pWh, *pH1, *pH2, *pHln, *pMid, *pFFo, *pSc1, *pSc2;
    float2* pC2;
    cudaGetSymbolAddress((void**)&pWh,  g_Wh);
    cudaGetSymbolAddress((void**)&pH1,  g_h1);
    cudaGetSymbolAddress((void**)&pH2,  g_h2);
    cudaGetSymbolAddress((void**)&pHln, g_hln);
    cudaGetSymbolAddress((void**)&pMid, g_mid);
    cudaGetSymbolAddress((void**)&pFFo, g_ff);
    cudaGetSymbolAddress((void**)&pSc1, g_sc1);
    cudaGetSymbolAddress((void**)&pSc2, g_sc2);
    cudaGetSymbolAddress((void**)&pC2,  g_c2);

    const int M = Bb * NN;   // 8192

    pack_bits<<<Bb * NN, 256>>>(adj);
    transpose_bits<<<512, 256>>>();

    // ---- GAT layer 1 ----
    gemm_tf32<0, true><<<dim3(M / 128, FF / 128), 256>>>(x, W1, nullptr, pWh, M, FF, FF);
    sc_kernel<<<M / 8, 256>>>(pWh, a1, pSc1, pSc2);
    colstats_part<<<dim3(NN / 256, NCHUNK, Bb), 256>>>(pSc1, pSc2);
    colstats_reduce<<<(Bb * NN) / 256, 256>>>(pSc2, pC2);
    agg_tf32<<<dim3(NN / 128, FF / 128, Bb), 256>>>(pWh, pSc1, pC2, pH1);

    // ---- GAT layer 2 ----
    gemm_tf32<0, true><<<dim3(M / 128, FF / 128), 256>>>(pH1, W2, nullptr, pWh, M, FF, FF);
    sc_kernel<<<M / 8, 256>>>(pWh, a2, pSc1, pSc2);
    colstats_part<<<dim3(NN / 256, NCHUNK, Bb), 256>>>(pSc1, pSc2);
    colstats_reduce<<<(Bb * NN) / 256, 256>>>(pSc2, pC2);
    agg_tf32<<<dim3(NN / 128, FF / 128, Bb), 256>>>(pWh, pSc1, pC2, pH2);

    // ---- residual + LN1 ----
    add_ln<<<M / 8, 256>>>(x, pH2, gln1, bln1, pHln);

    // ---- feed-forward (plain TF32: error budget has 200x margin) ----
    gemm_tf32<1, false><<<dim3(M / 128, HH / 128), 256>>>(pHln, wff1, bff1, pMid, M, HH, FF);
    gemm_tf32<2, false><<<dim3(M / 128, FF / 128), 256>>>(pMid, wff2, bff2, pFFo, M, FF, HH);

    // ---- residual + LN2 -> output ----
    add_ln<<<M / 8, 256>>>(pHln, pFFo, gln2, bln2, out);
}